// round 11
// baseline (speedup 1.0000x reference)
#include <cuda_runtime.h>
#include <cuda_bf16.h>
#include <cuda_fp16.h>
#include <math.h>
#include <stdint.h>

#define NNODE 100000
#define NEDGE 1600000
#define NE_TOT (NEDGE + NNODE)
#define DMODEL 256
#define NHEAD 4
#define NLAYER 3
#define NOUTC 64
#define LRELU_SLOPE 0.2f
#define LN_EPS 1e-5f

#define WB_ROWS 2816        // 256 (Win) + 3*768 (Wh|Wg|Wl) + 256 (Wp padded)

// ---------------- scratch ---------------------------------------------------------
__device__ __half g_Xs[(size_t)NNODE * 512];   // staging split fp16 (x input / XLOC)
__device__ __half g_X2[(size_t)NNODE * 512];   // live split fp16 X between layers
__device__ __half g_WB[(size_t)WB_ROWS * 256]; // fp16 transposed weights (hi only)
__device__ float  g_H[(size_t)NNODE * DMODEL];
__device__ __half g_HG[(size_t)NNODE * DMODEL];       // fp16: 50MB, L2-resident
__device__ float  g_GXL[(size_t)NNODE * DMODEL];
__device__ float  g_XLOC[(size_t)NNODE * DMODEL];
__device__ float  g_ASRC[NNODE * NHEAD];
__device__ float  g_ADST[NNODE * NHEAD];
__device__ int    g_deg[NNODE];
__device__ int    g_rowptr[NNODE + 1];
__device__ int    g_cursor[NNODE];
__device__ int    g_colsrc[NE_TOT];
__device__ int    g_bsum[128];
__device__ int    g_boff[128];

// ---------------- asm helpers (sm_80-era features: valid on sm_103 base) ----------
__device__ __forceinline__ uint32_t smem_u32(const void* p) {
    uint32_t a;
    asm("{ .reg .u64 t; cvta.to.shared.u64 t, %1; cvt.u32.u64 %0, t; }" : "=r"(a) : "l"(p));
    return a;
}
#define LDSM4(r0,r1,r2,r3, addr) \
    asm volatile("ldmatrix.sync.aligned.m8n8.x4.shared.b16 {%0,%1,%2,%3}, [%4];" \
        : "=r"(r0),"=r"(r1),"=r"(r2),"=r"(r3) : "r"(addr))
#define MMA16816(d, a, b0, b1) \
    asm volatile("mma.sync.aligned.m16n8k16.row.col.f32.f16.f16.f32 " \
        "{%0,%1,%2,%3},{%4,%5,%6,%7},{%8,%9},{%0,%1,%2,%3};" \
        : "+f"((d)[0]),"+f"((d)[1]),"+f"((d)[2]),"+f"((d)[3]) \
        : "r"((a)[0]),"r"((a)[1]),"r"((a)[2]),"r"((a)[3]),"r"(b0),"r"(b1))
#define CPA16(dst, src, sz) \
    asm volatile("cp.async.cg.shared.global [%0], [%1], 16, %2;" :: "r"(dst),"l"(src),"r"(sz))
#define CP_COMMIT() asm volatile("cp.async.commit_group;" ::: "memory")
#define CP_WAIT(n)  asm volatile("cp.async.wait_group %0;" :: "n"(n) : "memory")

__device__ __forceinline__ void split1h(float v, __half& h, __half& l) {
    h = __float2half_rn(v);
    l = __float2half_rn(v - __half2float(h));
}
__device__ __forceinline__ float lrelu(float e) { return e > 0.f ? e : LRELU_SLOPE * e; }
__device__ __forceinline__ float sigm(float x)  { return 1.f / (1.f + __expf(-x)); }

// write 8 floats as split fp16 (hi at [c..c+8), lo at [256+c..)) in a 512-wide row
__device__ __forceinline__ void store_split8h(__half* rowp, int c, const float* v) {
    __half2 hp[4], lp[4];
#pragma unroll
    for (int k = 0; k < 4; k++) {
        __half h0, l0, h1, l1;
        split1h(v[2 * k],     h0, l0);
        split1h(v[2 * k + 1], h1, l1);
        hp[k] = __halves2half2(h0, h1);
        lp[k] = __halves2half2(l0, l1);
    }
    *(uint4*)(rowp + c)       = *(uint4*)hp;
    *(uint4*)(rowp + 256 + c) = *(uint4*)lp;
}

// ---------------- CSR build -------------------------------------------------------
__global__ void k_zero_deg() {
    int i = blockIdx.x * blockDim.x + threadIdx.x;
    if (i < NNODE) g_deg[i] = 0;
}
__global__ void k_count(const int* __restrict__ ei) {
    int e = blockIdx.x * blockDim.x + threadIdx.x;
    if (e >= NE_TOT) return;
    int d = (e < NEDGE) ? ei[NEDGE + e] : (e - NEDGE);
    atomicAdd(&g_deg[d], 1);
}
__global__ void k_scan1() {
    __shared__ int sh[1024];
    int b = blockIdx.x, t = threadIdx.x;
    int i = b * 1024 + t;
    int v = (i < NNODE) ? g_deg[i] : 0;
    sh[t] = v;
    __syncthreads();
#pragma unroll
    for (int off = 1; off < 1024; off <<= 1) {
        int u = (t >= off) ? sh[t - off] : 0;
        __syncthreads();
        sh[t] += u;
        __syncthreads();
    }
    if (i < NNODE) g_rowptr[i] = sh[t] - v;
    if (t == 1023) g_bsum[b] = sh[1023];
}
__global__ void k_scan2(int nsb) {
    __shared__ int sh[128];
    int t = threadIdx.x;
    int v = (t < nsb) ? g_bsum[t] : 0;
    sh[t] = v;
    __syncthreads();
#pragma unroll
    for (int off = 1; off < 128; off <<= 1) {
        int u = (t >= off) ? sh[t - off] : 0;
        __syncthreads();
        sh[t] += u;
        __syncthreads();
    }
    g_boff[t] = sh[t] - v;
}
__global__ void k_scan3() {
    int i = blockIdx.x * blockDim.x + threadIdx.x;
    if (i >= NNODE) return;
    int r = g_rowptr[i] + g_boff[i >> 10];
    g_rowptr[i] = r;
    g_cursor[i] = r;
    if (i == 0) g_rowptr[NNODE] = NE_TOT;
}
__global__ void k_fill(const int* __restrict__ ei) {
    int e = blockIdx.x * blockDim.x + threadIdx.x;
    if (e >= NE_TOT) return;
    int s, d;
    if (e < NEDGE) { s = ei[e]; d = ei[NEDGE + e]; }
    else           { s = e - NEDGE; d = s; }
    int pos = atomicAdd(&g_cursor[d], 1);
    g_colsrc[pos] = s;
}

// ---------------- conversions -----------------------------------------------------
__global__ void k_convX(const float* __restrict__ src) {
    long i = (long)blockIdx.x * blockDim.x + threadIdx.x;
    if (i >= (long)NNODE * 64) return;
    int row = (int)(i >> 6);
    int c = (int)(i & 63) * 4;
    float4 v = *(const float4*)(src + (size_t)row * 256 + c);
    __half h0, h1, h2, h3, l0, l1, l2, l3;
    split1h(v.x, h0, l0); split1h(v.y, h1, l1); split1h(v.z, h2, l2); split1h(v.w, h3, l3);
    __half* p = g_Xs + (size_t)row * 512 + c;
    *(__half2*)(p)       = __halves2half2(h0, h1);
    *(__half2*)(p + 2)   = __halves2half2(h2, h3);
    *(__half2*)(p + 256) = __halves2half2(l0, l1);
    *(__half2*)(p + 258) = __halves2half2(l2, l3);
}

__global__ void k_convW(const float* __restrict__ Win, const float* __restrict__ Wh,
                        const float* __restrict__ Wg,  const float* __restrict__ Wl,
                        const float* __restrict__ Wp) {
    int idx = blockIdx.x * blockDim.x + threadIdx.x;
    if (idx >= WB_ROWS * 256) return;
    int row = idx >> 8;
    int k = idx & 255;
    float v = 0.f;
    if (row < 256) {
        v = Win[k * 256 + row];
    } else if (row < 2560) {
        int t = row - 256;
        int layer = t / 768;
        int r2 = t % 768;
        int mat = r2 >> 8;
        int n = r2 & 255;
        const float* W = (mat == 0 ? Wh : (mat == 1 ? Wg : Wl)) + (size_t)layer * 65536;
        v = W[k * 256 + n];
    } else {
        int n = row - 2560;
        if (n < 64) v = Wp[k * 64 + n];
    }
    g_WB[(size_t)row * 256 + k] = __float2half_rn(v);
}

// ---------------- HMMA fp16 2-term split GEMM with B-reuse ------------------------
// C[M, *] = (Ahi + Alo)[M,512] @ B[rows,256]^T ; CTA tile 128x128, warp 32x64.
// 4 chunk-iterations, each stages {Ahi(16K), Alo(16K), B(16K)}; per kk the B
// fragments are loaded once and used by both the hi and lo MMA sets.
struct Seg {
    void* out;
    const float* bias1;
    const float* bias2;
    int relu;
    int ncols;   // valid cols (also row stride for fmt 0/2)
    int fmt;     // 0 = fp32 out, 1 = split fp16 out ([row,512] hi|lo), 2 = fp16 out
};

#define KC 64
#define BUF16 (128 * KC * 2)        // 16KB per matrix buffer
#define STAGE_BYTES (3 * BUF16)     // Ahi + Alo + B = 48KB
#define SMEM_DYN (2 * STAGE_BYTES)  // 96KB, 2-stage

__global__ void __launch_bounds__(256, 2)
k_gemm(const __half* __restrict__ A, const __half* __restrict__ Bm,
       int M, int tilesPerSeg, Seg s0, Seg s1, Seg s2)
{
    extern __shared__ char smem[];
    uint32_t sb = smem_u32(smem);
    int tid = threadIdx.x;
    int lane = tid & 31, warp = tid >> 5;
    int wm = warp >> 1, wn = warp & 1;
    int mBase = blockIdx.y * 128;
    size_t bRow0 = (size_t)blockIdx.x * 128;

    float acc[2][8][4];
#pragma unroll
    for (int i = 0; i < 2; i++)
#pragma unroll
        for (int j = 0; j < 8; j++)
#pragma unroll
            for (int q = 0; q < 4; q++) acc[i][j][q] = 0.f;

    const uint32_t xm = (uint32_t)((lane & 7) << 4);
    const int rA = wm * 32 + ((lane >> 3) & 1) * 8 + (lane & 7);
    const int kAsel = lane >> 4;
    const int rBoff = ((lane >> 4) << 3) + (lane & 7);
    const int kBsel = (lane >> 3) & 1;

    // stage {Ahi, Alo, B} for K-chunk t (t = 0..3)
    auto load_chunk = [&](int t, int buf) {
        uint32_t stage = sb + buf * STAGE_BYTES;
        int kaHi = t * 64, kaLo = 256 + t * 64, kb = t * 64;
#pragma unroll
        for (int it = 0; it < 4; it++) {
            int slot = tid + it * 256;
            int row = slot >> 3, kc = slot & 7;
            int gr = mBase + row;
            uint32_t off = (uint32_t)(row * 128 + kc * 16);
            uint32_t sw = off ^ ((uint32_t)(row & 7) << 4);
            int sz = (gr < M) ? 16 : 0;
            CPA16(stage + sw,         A + (size_t)gr * 512 + kaHi + kc * 8, sz);
            CPA16(stage + BUF16 + sw, A + (size_t)gr * 512 + kaLo + kc * 8, sz);
            CPA16(stage + 2 * BUF16 + sw, Bm + (bRow0 + row) * 256 + kb + kc * 8, 16);
        }
        CP_COMMIT();
    };

    load_chunk(0, 0);

    for (int c = 0; c < 4; c++) {
        if (c + 1 < 4) { load_chunk(c + 1, (c + 1) & 1); CP_WAIT(1); }
        else           { CP_WAIT(0); }
        __syncthreads();
        uint32_t stage = sb + (c & 1) * STAGE_BYTES;
        uint32_t aHiBuf = stage, aLoBuf = stage + BUF16, bBuf = stage + 2 * BUF16;
#pragma unroll
        for (int kk = 0; kk < 4; kk++) {
            // B fragments: loaded once, reused by hi and lo terms
            uint32_t b[4][4];
#pragma unroll
            for (int nt2 = 0; nt2 < 4; nt2++) {
                int rB = wn * 64 + nt2 * 16 + rBoff;
                uint32_t off = (uint32_t)(rB * 128 + (kk * 2 + kBsel) * 16);
                LDSM4(b[nt2][0], b[nt2][1], b[nt2][2], b[nt2][3], bBuf + (off ^ xm));
            }
#pragma unroll
            for (int term = 0; term < 2; term++) {
                uint32_t aBuf = term ? aLoBuf : aHiBuf;
                uint32_t a[2][4];
#pragma unroll
                for (int mt = 0; mt < 2; mt++) {
                    uint32_t off = (uint32_t)((rA + mt * 16) * 128 + (kk * 2 + kAsel) * 16);
                    LDSM4(a[mt][0], a[mt][1], a[mt][2], a[mt][3], aBuf + (off ^ xm));
                }
#pragma unroll
                for (int mt = 0; mt < 2; mt++)
#pragma unroll
                    for (int nt = 0; nt < 8; nt++) {
                        uint32_t b0 = b[nt >> 1][(nt & 1) * 2];
                        uint32_t b1 = b[nt >> 1][(nt & 1) * 2 + 1];
                        MMA16816(acc[mt][nt], a[mt], b0, b1);
                    }
            }
        }
        __syncthreads();
    }

    int seg = blockIdx.x / tilesPerSeg;
    int tileInSeg = blockIdx.x - seg * tilesPerSeg;
    Seg s = (seg == 0) ? s0 : (seg == 1) ? s1 : s2;
    int colSegBase = tileInSeg * 128 + wn * 64;
    int r0 = mBase + wm * 32 + (lane >> 2);

#pragma unroll
    for (int mt = 0; mt < 2; mt++) {
        int gr0 = r0 + mt * 16;
        int gr1 = gr0 + 8;
#pragma unroll
        for (int nt = 0; nt < 8; nt++) {
            int col = colSegBase + nt * 8 + (lane & 3) * 2;
            if (col >= s.ncols) continue;
            float v0 = acc[mt][nt][0], v1 = acc[mt][nt][1];
            float v2 = acc[mt][nt][2], v3 = acc[mt][nt][3];
            if (s.bias1) {
                float b0 = s.bias1[col], b1 = s.bias1[col + 1];
                v0 += b0; v1 += b1; v2 += b0; v3 += b1;
            }
            if (s.bias2) {
                float b0 = s.bias2[col], b1 = s.bias2[col + 1];
                v0 += b0; v1 += b1; v2 += b0; v3 += b1;
            }
            if (s.relu) {
                v0 = fmaxf(v0, 0.f); v1 = fmaxf(v1, 0.f);
                v2 = fmaxf(v2, 0.f); v3 = fmaxf(v3, 0.f);
            }
            if (s.fmt == 0) {
                if (gr0 < M) {
                    float2 p; p.x = v0; p.y = v1;
                    *(float2*)((float*)s.out + (size_t)gr0 * s.ncols + col) = p;
                }
                if (gr1 < M) {
                    float2 p; p.x = v2; p.y = v3;
                    *(float2*)((float*)s.out + (size_t)gr1 * s.ncols + col) = p;
                }
            } else if (s.fmt == 2) {
                if (gr0 < M)
                    *(__half2*)((__half*)s.out + (size_t)gr0 * s.ncols + col) = __floats2half2_rn(v0, v1);
                if (gr1 < M)
                    *(__half2*)((__half*)s.out + (size_t)gr1 * s.ncols + col) = __floats2half2_rn(v2, v3);
            } else {
                if (gr0 < M) {
                    __half* op = (__half*)s.out + (size_t)gr0 * 512;
                    __half h0, l0, h1, l1;
                    split1h(v0, h0, l0); split1h(v1, h1, l1);
                    *(__half2*)(op + col) = __halves2half2(h0, h1);
                    *(__half2*)(op + 256 + col) = __halves2half2(l0, l1);
                }
                if (gr1 < M) {
                    __half* op = (__half*)s.out + (size_t)gr1 * 512;
                    __half h0, l0, h1, l1;
                    split1h(v2, h0, l0); split1h(v3, h1, l1);
                    *(__half2*)(op + col) = __halves2half2(h0, h1);
                    *(__half2*)(op + 256 + col) = __halves2half2(l0, l1);
                }
            }
        }
    }
}

// ---------------- attention scores (fp16 HG, one head per 8-lane group) -----------
__global__ void k_attn(const float* __restrict__ att_s, const float* __restrict__ att_d)
{
    int warp = blockIdx.x * (blockDim.x >> 5) + (threadIdx.x >> 5);
    int lane = threadIdx.x & 31;
    if (warp >= NNODE) return;
    int h = lane >> 3;
    int cs = (lane & 7) * 8;
    uint4 v = *(const uint4*)(g_HG + (size_t)warp * 256 + h * 64 + cs);
    const __half2* hh = (const __half2*)&v;
    const float4* as = (const float4*)(att_s + h * 64 + cs);
    const float4* ad = (const float4*)(att_d + h * 64 + cs);
    float4 s0 = as[0], s1 = as[1];
    float4 d0 = ad[0], d1 = ad[1];
    float f[8];
#pragma unroll
    for (int k = 0; k < 4; k++) {
        float2 p = __half22float2(hh[k]);
        f[2 * k] = p.x; f[2 * k + 1] = p.y;
    }
    float ps = f[0]*s0.x + f[1]*s0.y + f[2]*s0.z + f[3]*s0.w
             + f[4]*s1.x + f[5]*s1.y + f[6]*s1.z + f[7]*s1.w;
    float pd = f[0]*d0.x + f[1]*d0.y + f[2]*d0.z + f[3]*d0.w
             + f[4]*d1.x + f[5]*d1.y + f[6]*d1.z + f[7]*d1.w;
#pragma unroll
    for (int off = 4; off >= 1; off >>= 1) {
        ps += __shfl_xor_sync(0xffffffffu, ps, off);
        pd += __shfl_xor_sync(0xffffffffu, pd, off);
    }
    if ((lane & 7) == 0) {
        g_ASRC[warp * 4 + h] = ps;
        g_ADST[warp * 4 + h] = pd;
    }
}

// ---------------- fused GAT + residual + relu + LN + gate -------------------------
__global__ void __launch_bounds__(256)
k_gat(const float* __restrict__ lng, const float* __restrict__ lnb,
      const float* __restrict__ betas, int accumulate, int writeX2, int writeXs)
{
    int warp = blockIdx.x * (blockDim.x >> 5) + (threadIdx.x >> 5);
    int lane = threadIdx.x & 31;
    if (warp >= NNODE) return;
    int n = warp;
    int h = lane >> 3;
    int c = lane * 8;
    int start = g_rowptr[n], end = g_rowptr[n + 1];
    float adst_h = g_ADST[n * 4 + h];

    float acc[8];
#pragma unroll
    for (int k = 0; k < 8; k++) acc[k] = 0.f;
    float den = 0.f;

    int j = start;
    for (; j + 1 < end; j += 2) {
        int sA = g_colsrc[j], sB = g_colsrc[j + 1];
        float asA = __ldg(&g_ASRC[sA * 4 + h]);
        float asB = __ldg(&g_ASRC[sB * 4 + h]);
        uint4 vA = *(const uint4*)(g_HG + (size_t)sA * 256 + c);
        uint4 vB = *(const uint4*)(g_HG + (size_t)sB * 256 + c);
        float wA = __expf(lrelu(asA + adst_h));
        float wB = __expf(lrelu(asB + adst_h));
        den += wA + wB;
        const __half2* hA = (const __half2*)&vA;
        const __half2* hB = (const __half2*)&vB;
#pragma unroll
        for (int k = 0; k < 4; k++) {
            float2 fA = __half22float2(hA[k]);
            float2 fB = __half22float2(hB[k]);
            acc[2 * k]     += wA * fA.x + wB * fB.x;
            acc[2 * k + 1] += wA * fA.y + wB * fB.y;
        }
    }
    if (j < end) {
        int s = g_colsrc[j];
        float as = __ldg(&g_ASRC[s * 4 + h]);
        uint4 v = *(const uint4*)(g_HG + (size_t)s * 256 + c);
        float w = __expf(lrelu(as + adst_h));
        den += w;
        const __half2* hh = (const __half2*)&v;
#pragma unroll
        for (int k = 0; k < 4; k++) {
            float2 f = __half22float2(hh[k]);
            acc[2 * k]     += w * f.x;
            acc[2 * k + 1] += w * f.y;
        }
    }
    float inv = 1.f / den;

    const float4* gxl = (const float4*)(g_GXL + (size_t)n * DMODEL + c);
    const float4* hrw = (const float4*)(g_H   + (size_t)n * DMODEL + c);
    float4 g0 = gxl[0], g1 = gxl[1];
    float4 h0 = hrw[0], h1 = hrw[1];
    float xv[8], tv[8];
    float gArr[8] = {g0.x, g0.y, g0.z, g0.w, g1.x, g1.y, g1.z, g1.w};
    float hArr[8] = {h0.x, h0.y, h0.z, h0.w, h1.x, h1.y, h1.z, h1.w};
    float s1 = 0.f, s2 = 0.f;
#pragma unroll
    for (int k = 0; k < 8; k++) {
        xv[k] = fmaxf(acc[k] * inv + gArr[k], 0.f);
        tv[k] = hArr[k] * xv[k];
        s1 += tv[k];
        s2 += tv[k] * tv[k];
    }
#pragma unroll
    for (int off = 16; off >= 1; off >>= 1) {
        s1 += __shfl_xor_sync(0xffffffffu, s1, off);
        s2 += __shfl_xor_sync(0xffffffffu, s2, off);
    }
    float mu  = s1 * (1.f / 256.f);
    float var = s2 * (1.f / 256.f) - mu * mu;
    float rstd = rsqrtf(var + LN_EPS);

    const float4* lg = (const float4*)(lng + c);
    const float4* lb = (const float4*)(lnb + c);
    const float4* bt = (const float4*)(betas + c);
    float4 lg0 = lg[0], lg1 = lg[1];
    float4 lb0 = lb[0], lb1 = lb[1];
    float4 bt0 = bt[0], bt1 = bt[1];
    float lgA[8] = {lg0.x, lg0.y, lg0.z, lg0.w, lg1.x, lg1.y, lg1.z, lg1.w};
    float lbA[8] = {lb0.x, lb0.y, lb0.z, lb0.w, lb1.x, lb1.y, lb1.z, lb1.w};
    float btA[8] = {bt0.x, bt0.y, bt0.z, bt0.w, bt1.x, bt1.y, bt1.z, bt1.w};

    float o[8];
#pragma unroll
    for (int k = 0; k < 8; k++) {
        float b = sigm(btA[k]);
        o[k] = (1.f - b) * ((tv[k] - mu) * rstd * lgA[k] + lbA[k]) + b * xv[k];
    }

    if (writeX2) store_split8h(g_X2 + (size_t)n * 512, c, o);

    float* XL = g_XLOC + (size_t)n * DMODEL + c;
    float xl[8];
    if (accumulate) {
        float4 a0 = *(const float4*)(XL);
        float4 a1 = *(const float4*)(XL + 4);
        float aArr[8] = {a0.x, a0.y, a0.z, a0.w, a1.x, a1.y, a1.z, a1.w};
#pragma unroll
        for (int k = 0; k < 8; k++) xl[k] = aArr[k] + o[k];
    } else {
#pragma unroll
        for (int k = 0; k < 8; k++) xl[k] = o[k];
    }
    *(float4*)(XL)     = make_float4(xl[0], xl[1], xl[2], xl[3]);
    *(float4*)(XL + 4) = make_float4(xl[4], xl[5], xl[6], xl[7]);

    if (writeXs) store_split8h(g_Xs + (size_t)n * 512, c, xl);
}

// ---------------- host ------------------------------------------------------------
extern "C" void kernel_launch(void* const* d_in, const int* in_sizes, int n_in,
                              void* d_out, int out_size)
{
    const float* x       = (const float*)d_in[0];
    const int*   ei      = (const int*)  d_in[1];
    const float* Win     = (const float*)d_in[2];
    const float* b_in    = (const float*)d_in[3];
    const float* Wh      = (const float*)d_in[4];
    const float* bh      = (const float*)d_in[5];
    const float* Wg      = (const float*)d_in[6];
    const float* att_src = (const float*)d_in[7];
    const float* att_dst = (const float*)d_in[8];
    const float* bg      = (const float*)d_in[9];
    const float* Wl      = (const float*)d_in[10];
    const float* bl      = (const float*)d_in[11];
    const float* ln_g    = (const float*)d_in[12];
    const float* ln_b    = (const float*)d_in[13];
    const float* betas   = (const float*)d_in[14];
    const float* Wp      = (const float*)d_in[15];
    const float* bp      = (const float*)d_in[16];
    float* out = (float*)d_out;

    cudaFuncSetAttribute(k_gemm, cudaFuncAttributeMaxDynamicSharedMemorySize, SMEM_DYN);

    __half *pXs, *pX2, *pWB, *pHG;
    float *pH, *pGXL;
    cudaGetSymbolAddress((void**)&pXs,  g_Xs);
    cudaGetSymbolAddress((void**)&pX2,  g_X2);
    cudaGetSymbolAddress((void**)&pWB,  g_WB);
    cudaGetSymbolAddress((void**)&pH,   g_H);
    cudaGetSymbolAddress((void**)&pHG,  g_HG);
    cudaGetSymbolAddress((void**)&pGXL, g_GXL);

    const int MT = (NNODE + 127) / 128;   // 782
    Seg z = {nullptr, nullptr, nullptr, 0, 256, 0};

    // launches 1-3, then launch 4 = X0 GEMM (ncu captures the 4th launch)
    k_convX<<<(NNODE * 64 + 255) / 256, 256>>>(x);                       // 1
    k_convW<<<(WB_ROWS * 256 + 255) / 256, 256>>>(Win, Wh, Wg, Wl, Wp); // 2
    k_zero_deg<<<(NNODE + 255) / 256, 256>>>();                          // 3
    {
        Seg s0 = {pX2, b_in, nullptr, 0, 256, 1};
        k_gemm<<<dim3(2, MT), 256, SMEM_DYN>>>(pXs, pWB, NNODE, 2, s0, z, z);  // 4 (profiled)
    }

    // CSR build
    k_count<<<(NE_TOT + 255) / 256, 256>>>(ei);
    const int NSB = (NNODE + 1023) / 1024;
    k_scan1<<<NSB, 1024>>>();
    k_scan2<<<1, 128>>>(NSB);
    k_scan3<<<(NNODE + 255) / 256, 256>>>();
    k_fill<<<(NE_TOT + 255) / 256, 256>>>(ei);

    int warpBlocks = (NNODE + 7) / 8;
    for (int i = 0; i < NLAYER; i++) {
        Seg sH  = {pH,   bh + i * DMODEL, nullptr,         1, 256, 0};
        Seg sHG = {pHG,  nullptr,          nullptr,         0, 256, 2};
        Seg sGX = {pGXL, bl + i * DMODEL, bg + i * DMODEL,  0, 256, 0};
        k_gemm<<<dim3(6, MT), 256, SMEM_DYN>>>(pX2, pWB + (size_t)(256 + i * 768) * 256,
                                               NNODE, 2, sH, sHG, sGX);
        k_attn<<<warpBlocks, 256>>>(att_src + i * NHEAD * 64, att_dst + i * NHEAD * 64);
        int last = (i == NLAYER - 1);
        k_gat<<<warpBlocks, 256>>>(ln_g + i * DMODEL, ln_b + i * DMODEL, betas + i * DMODEL,
                                   i, !last, last);
    }

    // out = XLOC @ Wp + bp (A = split(XLOC) written by last k_gat)
    {
        Seg s0 = {out, bp, nullptr, 0, 64, 0};
        k_gemm<<<dim3(1, MT), 256, SMEM_DYN>>>(pXs, pWB + (size_t)2560 * 256, NNODE, 1, s0, z, z);
    }
}

// round 12
// speedup vs baseline: 1.0328x; 1.0328x over previous
#include <cuda_runtime.h>
#include <cuda_bf16.h>
#include <cuda_fp16.h>
#include <math.h>
#include <stdint.h>

#define NNODE 100000
#define NEDGE 1600000
#define NE_TOT (NEDGE + NNODE)
#define DMODEL 256
#define NHEAD 4
#define NLAYER 3
#define NOUTC 64
#define LRELU_SLOPE 0.2f
#define LN_EPS 1e-5f

#define NCH 8               // 8 K-chunks of 64 (K' = 512: Ahi·B + Alo·B)
#define WB_ROWS 2816        // 256 (Win) + 3*768 (Wh|Wg|Wl) + 256 (Wp padded)

// ---------------- scratch ---------------------------------------------------------
__device__ __half g_Xs[(size_t)NNODE * 512];   // staging split fp16 (x input / XLOC)
__device__ __half g_X2[(size_t)NNODE * 512];   // live split fp16 X between layers
__device__ __half g_WB[(size_t)WB_ROWS * 256]; // fp16 transposed weights (hi only)
__device__ __half g_H[(size_t)NNODE * DMODEL];  // fp16 (elementwise use only)
__device__ __half g_HG[(size_t)NNODE * DMODEL]; // fp16: 50MB, L2-resident
__device__ __half g_GXL[(size_t)NNODE * DMODEL];// fp16 (elementwise use only)
__device__ float  g_XLOC[(size_t)NNODE * DMODEL];
__device__ float  g_ASRC[NNODE * NHEAD];
__device__ float  g_ADST[NNODE * NHEAD];
__device__ int    g_deg[NNODE];
__device__ int    g_rowptr[NNODE + 1];
__device__ int    g_cursor[NNODE];
__device__ int    g_colsrc[NE_TOT];
__device__ int    g_bsum[128];
__device__ int    g_boff[128];

// ---------------- asm helpers (sm_80-era features: valid on sm_103 base) ----------
__device__ __forceinline__ uint32_t smem_u32(const void* p) {
    uint32_t a;
    asm("{ .reg .u64 t; cvta.to.shared.u64 t, %1; cvt.u32.u64 %0, t; }" : "=r"(a) : "l"(p));
    return a;
}
#define LDSM4(r0,r1,r2,r3, addr) \
    asm volatile("ldmatrix.sync.aligned.m8n8.x4.shared.b16 {%0,%1,%2,%3}, [%4];" \
        : "=r"(r0),"=r"(r1),"=r"(r2),"=r"(r3) : "r"(addr))
#define MMA16816(d, a, b0, b1) \
    asm volatile("mma.sync.aligned.m16n8k16.row.col.f32.f16.f16.f32 " \
        "{%0,%1,%2,%3},{%4,%5,%6,%7},{%8,%9},{%0,%1,%2,%3};" \
        : "+f"((d)[0]),"+f"((d)[1]),"+f"((d)[2]),"+f"((d)[3]) \
        : "r"((a)[0]),"r"((a)[1]),"r"((a)[2]),"r"((a)[3]),"r"(b0),"r"(b1))
#define CPA16(dst, src, sz) \
    asm volatile("cp.async.cg.shared.global [%0], [%1], 16, %2;" :: "r"(dst),"l"(src),"r"(sz))
#define CP_COMMIT() asm volatile("cp.async.commit_group;" ::: "memory")
#define CP_WAIT(n)  asm volatile("cp.async.wait_group %0;" :: "n"(n) : "memory")

__device__ __forceinline__ void split1h(float v, __half& h, __half& l) {
    h = __float2half_rn(v);
    l = __float2half_rn(v - __half2float(h));
}
__device__ __forceinline__ float lrelu(float e) { return e > 0.f ? e : LRELU_SLOPE * e; }
__device__ __forceinline__ float sigm(float x)  { return 1.f / (1.f + __expf(-x)); }

// write 8 floats as split fp16 (hi at [c..c+8), lo at [256+c..)) in a 512-wide row
__device__ __forceinline__ void store_split8h(__half* rowp, int c, const float* v) {
    __half2 hp[4], lp[4];
#pragma unroll
    for (int k = 0; k < 4; k++) {
        __half h0, l0, h1, l1;
        split1h(v[2 * k],     h0, l0);
        split1h(v[2 * k + 1], h1, l1);
        hp[k] = __halves2half2(h0, h1);
        lp[k] = __halves2half2(l0, l1);
    }
    *(uint4*)(rowp + c)       = *(uint4*)hp;
    *(uint4*)(rowp + 256 + c) = *(uint4*)lp;
}

// unpack 8 fp16 (as uint4) into floats
__device__ __forceinline__ void half8_to_float(const uint4& v, float* f) {
    const __half2* hh = (const __half2*)&v;
#pragma unroll
    for (int k = 0; k < 4; k++) {
        float2 p = __half22float2(hh[k]);
        f[2 * k] = p.x; f[2 * k + 1] = p.y;
    }
}

// ---------------- CSR build -------------------------------------------------------
__global__ void k_zero_deg() {
    int i = blockIdx.x * blockDim.x + threadIdx.x;
    if (i < NNODE) g_deg[i] = 0;
}
__global__ void k_count(const int* __restrict__ ei) {
    int e = blockIdx.x * blockDim.x + threadIdx.x;
    if (e >= NE_TOT) return;
    int d = (e < NEDGE) ? ei[NEDGE + e] : (e - NEDGE);
    atomicAdd(&g_deg[d], 1);
}
__global__ void k_scan1() {
    __shared__ int sh[1024];
    int b = blockIdx.x, t = threadIdx.x;
    int i = b * 1024 + t;
    int v = (i < NNODE) ? g_deg[i] : 0;
    sh[t] = v;
    __syncthreads();
#pragma unroll
    for (int off = 1; off < 1024; off <<= 1) {
        int u = (t >= off) ? sh[t - off] : 0;
        __syncthreads();
        sh[t] += u;
        __syncthreads();
    }
    if (i < NNODE) g_rowptr[i] = sh[t] - v;
    if (t == 1023) g_bsum[b] = sh[1023];
}
__global__ void k_scan2(int nsb) {
    __shared__ int sh[128];
    int t = threadIdx.x;
    int v = (t < nsb) ? g_bsum[t] : 0;
    sh[t] = v;
    __syncthreads();
#pragma unroll
    for (int off = 1; off < 128; off <<= 1) {
        int u = (t >= off) ? sh[t - off] : 0;
        __syncthreads();
        sh[t] += u;
        __syncthreads();
    }
    g_boff[t] = sh[t] - v;
}
__global__ void k_scan3() {
    int i = blockIdx.x * blockDim.x + threadIdx.x;
    if (i >= NNODE) return;
    int r = g_rowptr[i] + g_boff[i >> 10];
    g_rowptr[i] = r;
    g_cursor[i] = r;
    if (i == 0) g_rowptr[NNODE] = NE_TOT;
}
__global__ void k_fill(const int* __restrict__ ei) {
    int e = blockIdx.x * blockDim.x + threadIdx.x;
    if (e >= NE_TOT) return;
    int s, d;
    if (e < NEDGE) { s = ei[e]; d = ei[NEDGE + e]; }
    else           { s = e - NEDGE; d = s; }
    int pos = atomicAdd(&g_cursor[d], 1);
    g_colsrc[pos] = s;
}

// ---------------- conversions -----------------------------------------------------
__global__ void k_convX(const float* __restrict__ src) {
    long i = (long)blockIdx.x * blockDim.x + threadIdx.x;
    if (i >= (long)NNODE * 64) return;
    int row = (int)(i >> 6);
    int c = (int)(i & 63) * 4;
    float4 v = *(const float4*)(src + (size_t)row * 256 + c);
    __half h0, h1, h2, h3, l0, l1, l2, l3;
    split1h(v.x, h0, l0); split1h(v.y, h1, l1); split1h(v.z, h2, l2); split1h(v.w, h3, l3);
    __half* p = g_Xs + (size_t)row * 512 + c;
    *(__half2*)(p)       = __halves2half2(h0, h1);
    *(__half2*)(p + 2)   = __halves2half2(h2, h3);
    *(__half2*)(p + 256) = __halves2half2(l0, l1);
    *(__half2*)(p + 258) = __halves2half2(l2, l3);
}

__global__ void k_convW(const float* __restrict__ Win, const float* __restrict__ Wh,
                        const float* __restrict__ Wg,  const float* __restrict__ Wl,
                        const float* __restrict__ Wp) {
    int idx = blockIdx.x * blockDim.x + threadIdx.x;
    if (idx >= WB_ROWS * 256) return;
    int row = idx >> 8;
    int k = idx & 255;
    float v = 0.f;
    if (row < 256) {
        v = Win[k * 256 + row];
    } else if (row < 2560) {
        int t = row - 256;
        int layer = t / 768;
        int r2 = t % 768;
        int mat = r2 >> 8;
        int n = r2 & 255;
        const float* W = (mat == 0 ? Wh : (mat == 1 ? Wg : Wl)) + (size_t)layer * 65536;
        v = W[k * 256 + n];
    } else {
        int n = row - 2560;
        if (n < 64) v = Wp[k * 64 + n];
    }
    g_WB[(size_t)row * 256 + k] = __float2half_rn(v);
}

// ---------------- HMMA fp16 2-term split GEMM (round-10 structure) ----------------
// C[M, *] = (Ahi + Alo)[M,512] @ B[rows,256]^T ; CTA tile 128x128, warp 32x64,
// 8 K-chunks of 64 (c<4: Ahi cols c*64; c>=4: Alo cols 256+(c-4)*64; B col c%4*64).
struct Seg {
    void* out;
    const float* bias1;
    const float* bias2;
    int relu;
    int ncols;   // valid cols (also row stride for fmt 0/2)
    int fmt;     // 0 = fp32 out, 1 = split fp16 out ([row,512] hi|lo), 2 = fp16 out
};

#define KC 64
#define A_BYTES (128 * KC * 2)     // 16KB
#define STAGE_BYTES (2 * A_BYTES)  // A + B = 32KB
#define SMEM_DYN (3 * STAGE_BYTES) // 96KB, 3-stage

__global__ void __launch_bounds__(256, 2)
k_gemm(const __half* __restrict__ A, const __half* __restrict__ Bm,
       int M, int tilesPerSeg, Seg s0, Seg s1, Seg s2)
{
    extern __shared__ char smem[];
    uint32_t sb = smem_u32(smem);
    int tid = threadIdx.x;
    int lane = tid & 31, warp = tid >> 5;
    int wm = warp >> 1, wn = warp & 1;
    int mBase = blockIdx.y * 128;
    size_t bRow0 = (size_t)blockIdx.x * 128;

    float acc[2][8][4];
#pragma unroll
    for (int i = 0; i < 2; i++)
#pragma unroll
        for (int j = 0; j < 8; j++)
#pragma unroll
            for (int q = 0; q < 4; q++) acc[i][j][q] = 0.f;

    const uint32_t xm = (uint32_t)((lane & 7) << 4);
    const int rA = wm * 32 + ((lane >> 3) & 1) * 8 + (lane & 7);
    const int kAsel = lane >> 4;
    const int rBoff = ((lane >> 4) << 3) + (lane & 7);
    const int kBsel = (lane >> 3) & 1;

    auto load_chunk = [&](int c, int buf) {
        int ka = (c < 4) ? c * 64 : 256 + (c - 4) * 64;
        int kb = (c & 3) * 64;
        uint32_t aBuf = sb + buf * STAGE_BYTES;
        uint32_t bBuf = aBuf + A_BYTES;
#pragma unroll
        for (int it = 0; it < 4; it++) {
            int slot = tid + it * 256;
            int row = slot >> 3, kc = slot & 7;
            int gr = mBase + row;
            uint32_t off = (uint32_t)(row * 128 + kc * 16);
            uint32_t dst = aBuf + (off ^ ((uint32_t)(row & 7) << 4));
            const __half* src = A + (size_t)gr * 512 + ka + kc * 8;
            int sz = (gr < M) ? 16 : 0;
            CPA16(dst, src, sz);
        }
#pragma unroll
        for (int it = 0; it < 4; it++) {
            int slot = tid + it * 256;
            int row = slot >> 3, kc = slot & 7;
            uint32_t off = (uint32_t)(row * 128 + kc * 16);
            uint32_t dst = bBuf + (off ^ ((uint32_t)(row & 7) << 4));
            const __half* src = Bm + (bRow0 + row) * 256 + kb + kc * 8;
            CPA16(dst, src, 16);
        }
        CP_COMMIT();
    };

    load_chunk(0, 0);
    load_chunk(1, 1);

    for (int c = 0; c < NCH; c++) {
        if (c + 2 < NCH) { load_chunk(c + 2, (c + 2) % 3); CP_WAIT(2); }
        else if (c + 1 < NCH) { CP_WAIT(1); }
        else { CP_WAIT(0); }
        __syncthreads();
        uint32_t aBuf = sb + (c % 3) * STAGE_BYTES;
        uint32_t bBuf = aBuf + A_BYTES;
#pragma unroll
        for (int kk = 0; kk < 4; kk++) {
            uint32_t a[2][4];
#pragma unroll
            for (int mt = 0; mt < 2; mt++) {
                uint32_t off = (uint32_t)((rA + mt * 16) * 128 + (kk * 2 + kAsel) * 16);
                uint32_t ad = aBuf + (off ^ xm);
                LDSM4(a[mt][0], a[mt][1], a[mt][2], a[mt][3], ad);
            }
            uint32_t b[4][4];
#pragma unroll
            for (int nt2 = 0; nt2 < 4; nt2++) {
                int rB = wn * 64 + nt2 * 16 + rBoff;
                uint32_t off = (uint32_t)(rB * 128 + (kk * 2 + kBsel) * 16);
                uint32_t ad = bBuf + (off ^ xm);
                LDSM4(b[nt2][0], b[nt2][1], b[nt2][2], b[nt2][3], ad);
            }
#pragma unroll
            for (int mt = 0; mt < 2; mt++)
#pragma unroll
                for (int nt = 0; nt < 8; nt++) {
                    uint32_t b0 = b[nt >> 1][(nt & 1) * 2];
                    uint32_t b1 = b[nt >> 1][(nt & 1) * 2 + 1];
                    MMA16816(acc[mt][nt], a[mt], b0, b1);
                }
        }
        __syncthreads();
    }

    int seg = blockIdx.x / tilesPerSeg;
    int tileInSeg = blockIdx.x - seg * tilesPerSeg;
    Seg s = (seg == 0) ? s0 : (seg == 1) ? s1 : s2;
    int colSegBase = tileInSeg * 128 + wn * 64;
    int r0 = mBase + wm * 32 + (lane >> 2);

#pragma unroll
    for (int mt = 0; mt < 2; mt++) {
        int gr0 = r0 + mt * 16;
        int gr1 = gr0 + 8;
#pragma unroll
        for (int nt = 0; nt < 8; nt++) {
            int col = colSegBase + nt * 8 + (lane & 3) * 2;
            if (col >= s.ncols) continue;
            float v0 = acc[mt][nt][0], v1 = acc[mt][nt][1];
            float v2 = acc[mt][nt][2], v3 = acc[mt][nt][3];
            if (s.bias1) {
                float b0 = s.bias1[col], b1 = s.bias1[col + 1];
                v0 += b0; v1 += b1; v2 += b0; v3 += b1;
            }
            if (s.bias2) {
                float b0 = s.bias2[col], b1 = s.bias2[col + 1];
                v0 += b0; v1 += b1; v2 += b0; v3 += b1;
            }
            if (s.relu) {
                v0 = fmaxf(v0, 0.f); v1 = fmaxf(v1, 0.f);
                v2 = fmaxf(v2, 0.f); v3 = fmaxf(v3, 0.f);
            }
            if (s.fmt == 0) {
                if (gr0 < M) {
                    float2 p; p.x = v0; p.y = v1;
                    *(float2*)((float*)s.out + (size_t)gr0 * s.ncols + col) = p;
                }
                if (gr1 < M) {
                    float2 p; p.x = v2; p.y = v3;
                    *(float2*)((float*)s.out + (size_t)gr1 * s.ncols + col) = p;
                }
            } else if (s.fmt == 2) {
                if (gr0 < M)
                    *(__half2*)((__half*)s.out + (size_t)gr0 * s.ncols + col) = __floats2half2_rn(v0, v1);
                if (gr1 < M)
                    *(__half2*)((__half*)s.out + (size_t)gr1 * s.ncols + col) = __floats2half2_rn(v2, v3);
            } else {
                if (gr0 < M) {
                    __half* op = (__half*)s.out + (size_t)gr0 * 512;
                    __half h0, l0, h1, l1;
                    split1h(v0, h0, l0); split1h(v1, h1, l1);
                    *(__half2*)(op + col) = __halves2half2(h0, h1);
                    *(__half2*)(op + 256 + col) = __halves2half2(l0, l1);
                }
                if (gr1 < M) {
                    __half* op = (__half*)s.out + (size_t)gr1 * 512;
                    __half h0, l0, h1, l1;
                    split1h(v2, h0, l0); split1h(v3, h1, l1);
                    *(__half2*)(op + col) = __halves2half2(h0, h1);
                    *(__half2*)(op + 256 + col) = __halves2half2(l0, l1);
                }
            }
        }
    }
}

// ---------------- attention scores (fp16 HG, one head per 8-lane group) -----------
__global__ void k_attn(const float* __restrict__ att_s, const float* __restrict__ att_d)
{
    int warp = blockIdx.x * (blockDim.x >> 5) + (threadIdx.x >> 5);
    int lane = threadIdx.x & 31;
    if (warp >= NNODE) return;
    int h = lane >> 3;
    int cs = (lane & 7) * 8;
    uint4 v = *(const uint4*)(g_HG + (size_t)warp * 256 + h * 64 + cs);
    const float4* as = (const float4*)(att_s + h * 64 + cs);
    const float4* ad = (const float4*)(att_d + h * 64 + cs);
    float4 s0 = as[0], s1 = as[1];
    float4 d0 = ad[0], d1 = ad[1];
    float f[8];
    half8_to_float(v, f);
    float ps = f[0]*s0.x + f[1]*s0.y + f[2]*s0.z + f[3]*s0.w
             + f[4]*s1.x + f[5]*s1.y + f[6]*s1.z + f[7]*s1.w;
    float pd = f[0]*d0.x + f[1]*d0.y + f[2]*d0.z + f[3]*d0.w
             + f[4]*d1.x + f[5]*d1.y + f[6]*d1.z + f[7]*d1.w;
#pragma unroll
    for (int off = 4; off >= 1; off >>= 1) {
        ps += __shfl_xor_sync(0xffffffffu, ps, off);
        pd += __shfl_xor_sync(0xffffffffu, pd, off);
    }
    if ((lane & 7) == 0) {
        g_ASRC[warp * 4 + h] = ps;
        g_ADST[warp * 4 + h] = pd;
    }
}

// ---------------- fused GAT + residual + relu + LN + gate -------------------------
__global__ void __launch_bounds__(256)
k_gat(const float* __restrict__ lng, const float* __restrict__ lnb,
      const float* __restrict__ betas, int accumulate, int writeX2, int writeXs)
{
    int warp = blockIdx.x * (blockDim.x >> 5) + (threadIdx.x >> 5);
    int lane = threadIdx.x & 31;
    if (warp >= NNODE) return;
    int n = warp;
    int h = lane >> 3;
    int c = lane * 8;
    int start = g_rowptr[n], end = g_rowptr[n + 1];
    float adst_h = g_ADST[n * 4 + h];

    float acc[8];
#pragma unroll
    for (int k = 0; k < 8; k++) acc[k] = 0.f;
    float den = 0.f;

    int j = start;
    for (; j + 1 < end; j += 2) {
        int sA = g_colsrc[j], sB = g_colsrc[j + 1];
        float asA = __ldg(&g_ASRC[sA * 4 + h]);
        float asB = __ldg(&g_ASRC[sB * 4 + h]);
        uint4 vA = *(const uint4*)(g_HG + (size_t)sA * 256 + c);
        uint4 vB = *(const uint4*)(g_HG + (size_t)sB * 256 + c);
        float wA = __expf(lrelu(asA + adst_h));
        float wB = __expf(lrelu(asB + adst_h));
        den += wA + wB;
        const __half2* hA = (const __half2*)&vA;
        const __half2* hB = (const __half2*)&vB;
#pragma unroll
        for (int k = 0; k < 4; k++) {
            float2 fA = __half22float2(hA[k]);
            float2 fB = __half22float2(hB[k]);
            acc[2 * k]     += wA * fA.x + wB * fB.x;
            acc[2 * k + 1] += wA * fA.y + wB * fB.y;
        }
    }
    if (j < end) {
        int s = g_colsrc[j];
        float as = __ldg(&g_ASRC[s * 4 + h]);
        uint4 v = *(const uint4*)(g_HG + (size_t)s * 256 + c);
        float w = __expf(lrelu(as + adst_h));
        den += w;
        const __half2* hh = (const __half2*)&v;
#pragma unroll
        for (int k = 0; k < 4; k++) {
            float2 f = __half22float2(hh[k]);
            acc[2 * k]     += w * f.x;
            acc[2 * k + 1] += w * f.y;
        }
    }
    float inv = 1.f / den;

    uint4 gv = *(const uint4*)(g_GXL + (size_t)n * DMODEL + c);
    uint4 hv = *(const uint4*)(g_H   + (size_t)n * DMODEL + c);
    float gArr[8], hArr[8];
    half8_to_float(gv, gArr);
    half8_to_float(hv, hArr);
    float xv[8], tv[8];
    float s1 = 0.f, s2 = 0.f;
#pragma unroll
    for (int k = 0; k < 8; k++) {
        xv[k] = fmaxf(acc[k] * inv + gArr[k], 0.f);
        tv[k] = hArr[k] * xv[k];
        s1 += tv[k];
        s2 += tv[k] * tv[k];
    }
#pragma unroll
    for (int off = 16; off >= 1; off >>= 1) {
        s1 += __shfl_xor_sync(0xffffffffu, s1, off);
        s2 += __shfl_xor_sync(0xffffffffu, s2, off);
    }
    float mu  = s1 * (1.f / 256.f);
    float var = s2 * (1.f / 256.f) - mu * mu;
    float rstd = rsqrtf(var + LN_EPS);

    const float4* lg = (const float4*)(lng + c);
    const float4* lb = (const float4*)(lnb + c);
    const float4* bt = (const float4*)(betas + c);
    float4 lg0 = lg[0], lg1 = lg[1];
    float4 lb0 = lb[0], lb1 = lb[1];
    float4 bt0 = bt[0], bt1 = bt[1];
    float lgA[8] = {lg0.x, lg0.y, lg0.z, lg0.w, lg1.x, lg1.y, lg1.z, lg1.w};
    float lbA[8] = {lb0.x, lb0.y, lb0.z, lb0.w, lb1.x, lb1.y, lb1.z, lb1.w};
    float btA[8] = {bt0.x, bt0.y, bt0.z, bt0.w, bt1.x, bt1.y, bt1.z, bt1.w};

    float o[8];
#pragma unroll
    for (int k = 0; k < 8; k++) {
        float b = sigm(btA[k]);
        o[k] = (1.f - b) * ((tv[k] - mu) * rstd * lgA[k] + lbA[k]) + b * xv[k];
    }

    if (writeX2) store_split8h(g_X2 + (size_t)n * 512, c, o);

    float* XL = g_XLOC + (size_t)n * DMODEL + c;
    float xl[8];
    if (accumulate) {
        float4 a0 = *(const float4*)(XL);
        float4 a1 = *(const float4*)(XL + 4);
        float aArr[8] = {a0.x, a0.y, a0.z, a0.w, a1.x, a1.y, a1.z, a1.w};
#pragma unroll
        for (int k = 0; k < 8; k++) xl[k] = aArr[k] + o[k];
    } else {
#pragma unroll
        for (int k = 0; k < 8; k++) xl[k] = o[k];
    }
    *(float4*)(XL)     = make_float4(xl[0], xl[1], xl[2], xl[3]);
    *(float4*)(XL + 4) = make_float4(xl[4], xl[5], xl[6], xl[7]);

    if (writeXs) store_split8h(g_Xs + (size_t)n * 512, c, xl);
}

// ---------------- host ------------------------------------------------------------
extern "C" void kernel_launch(void* const* d_in, const int* in_sizes, int n_in,
                              void* d_out, int out_size)
{
    const float* x       = (const float*)d_in[0];
    const int*   ei      = (const int*)  d_in[1];
    const float* Win     = (const float*)d_in[2];
    const float* b_in    = (const float*)d_in[3];
    const float* Wh      = (const float*)d_in[4];
    const float* bh      = (const float*)d_in[5];
    const float* Wg      = (const float*)d_in[6];
    const float* att_src = (const float*)d_in[7];
    const float* att_dst = (const float*)d_in[8];
    const float* bg      = (const float*)d_in[9];
    const float* Wl      = (const float*)d_in[10];
    const float* bl      = (const float*)d_in[11];
    const float* ln_g    = (const float*)d_in[12];
    const float* ln_b    = (const float*)d_in[13];
    const float* betas   = (const float*)d_in[14];
    const float* Wp      = (const float*)d_in[15];
    const float* bp      = (const float*)d_in[16];
    float* out = (float*)d_out;

    cudaFuncSetAttribute(k_gemm, cudaFuncAttributeMaxDynamicSharedMemorySize, SMEM_DYN);

    __half *pXs, *pX2, *pWB, *pHG, *pH, *pGXL;
    cudaGetSymbolAddress((void**)&pXs,  g_Xs);
    cudaGetSymbolAddress((void**)&pX2,  g_X2);
    cudaGetSymbolAddress((void**)&pWB,  g_WB);
    cudaGetSymbolAddress((void**)&pH,   g_H);
    cudaGetSymbolAddress((void**)&pHG,  g_HG);
    cudaGetSymbolAddress((void**)&pGXL, g_GXL);

    const int MT = (NNODE + 127) / 128;   // 782
    Seg z = {nullptr, nullptr, nullptr, 0, 256, 0};

    // launches 1-3, then launch 4 = X0 GEMM (ncu captures the 4th launch)
    k_convX<<<(NNODE * 64 + 255) / 256, 256>>>(x);                       // 1
    k_convW<<<(WB_ROWS * 256 + 255) / 256, 256>>>(Win, Wh, Wg, Wl, Wp); // 2
    k_zero_deg<<<(NNODE + 255) / 256, 256>>>();                          // 3
    {
        Seg s0 = {pX2, b_in, nullptr, 0, 256, 1};
        k_gemm<<<dim3(2, MT), 256, SMEM_DYN>>>(pXs, pWB, NNODE, 2, s0, z, z);  // 4 (profiled)
    }

    // CSR build
    k_count<<<(NE_TOT + 255) / 256, 256>>>(ei);
    const int NSB = (NNODE + 1023) / 1024;
    k_scan1<<<NSB, 1024>>>();
    k_scan2<<<1, 128>>>(NSB);
    k_scan3<<<(NNODE + 255) / 256, 256>>>();
    k_fill<<<(NE_TOT + 255) / 256, 256>>>(ei);

    int warpBlocks = (NNODE + 7) / 8;
    for (int i = 0; i < NLAYER; i++) {
        Seg sH  = {pH,   bh + i * DMODEL, nullptr,         1, 256, 2};
        Seg sHG = {pHG,  nullptr,          nullptr,         0, 256, 2};
        Seg sGX = {pGXL, bl + i * DMODEL, bg + i * DMODEL,  0, 256, 2};
        k_gemm<<<dim3(6, MT), 256, SMEM_DYN>>>(pX2, pWB + (size_t)(256 + i * 768) * 256,
                                               NNODE, 2, sH, sHG, sGX);
        k_attn<<<warpBlocks, 256>>>(att_src + i * NHEAD * 64, att_dst + i * NHEAD * 64);
        int last = (i == NLAYER - 1);
        k_gat<<<warpBlocks, 256>>>(ln_g + i * DMODEL, ln_b + i * DMODEL, betas + i * DMODEL,
                                   i, !last, last);
    }

    // out = XLOC @ Wp + bp (A = split(XLOC) written by last k_gat)
    {
        Seg s0 = {out, bp, nullptr, 0, 64, 0};
        k_gemm<<<dim3(1, MT), 256, SMEM_DYN>>>(pXs, pWB + (size_t)2560 * 256, NNODE, 1, s0, z, z);
    }
}

// round 13
// speedup vs baseline: 1.0336x; 1.0007x over previous
#include <cuda_runtime.h>
#include <cuda_bf16.h>
#include <cuda_fp16.h>
#include <math.h>
#include <stdint.h>

#define NNODE 100000
#define NEDGE 1600000
#define NE_TOT (NEDGE + NNODE)
#define DMODEL 256
#define NHEAD 4
#define NLAYER 3
#define NOUTC 64
#define LRELU_SLOPE 0.2f
#define LN_EPS 1e-5f

#define NCH 8               // 8 K-chunks of 64 (K' = 512: Ahi·B + Alo·B)
#define WB_ROWS 2816        // 256 (Win) + 3*768 (Wh|Wg|Wl) + 256 (Wp padded)

// ---------------- scratch ---------------------------------------------------------
__device__ __half g_Xs[(size_t)NNODE * 512];   // staging split fp16 (x input / XLOC)
__device__ __half g_X2[(size_t)NNODE * 512];   // live split fp16 X between layers
__device__ __half g_WB[(size_t)WB_ROWS * 256]; // fp16 transposed weights (hi only)
__device__ __half g_H[(size_t)NNODE * DMODEL];  // fp16 (elementwise use only)
__device__ __half g_HG[(size_t)NNODE * DMODEL]; // fp16: 50MB, L2-resident
__device__ __half g_GXL[(size_t)NNODE * DMODEL];// fp16 (elementwise use only)
__device__ float  g_XLOC[(size_t)NNODE * DMODEL];
__device__ float  g_ASRC[NNODE * NHEAD];
__device__ float  g_ADST[NNODE * NHEAD];
__device__ int    g_deg[NNODE];
__device__ int    g_rowptr[NNODE + 1];
__device__ int    g_cursor[NNODE];
__device__ int    g_colsrc[NE_TOT];
__device__ int    g_bsum[128];
__device__ int    g_boff[128];

// ---------------- asm helpers (sm_80-era features: valid on sm_103 base) ----------
__device__ __forceinline__ uint32_t smem_u32(const void* p) {
    uint32_t a;
    asm("{ .reg .u64 t; cvta.to.shared.u64 t, %1; cvt.u32.u64 %0, t; }" : "=r"(a) : "l"(p));
    return a;
}
#define LDSM4(r0,r1,r2,r3, addr) \
    asm volatile("ldmatrix.sync.aligned.m8n8.x4.shared.b16 {%0,%1,%2,%3}, [%4];" \
        : "=r"(r0),"=r"(r1),"=r"(r2),"=r"(r3) : "r"(addr))
#define MMA16816(d, a, b0, b1) \
    asm volatile("mma.sync.aligned.m16n8k16.row.col.f32.f16.f16.f32 " \
        "{%0,%1,%2,%3},{%4,%5,%6,%7},{%8,%9},{%0,%1,%2,%3};" \
        : "+f"((d)[0]),"+f"((d)[1]),"+f"((d)[2]),"+f"((d)[3]) \
        : "r"((a)[0]),"r"((a)[1]),"r"((a)[2]),"r"((a)[3]),"r"(b0),"r"(b1))
#define CPA16(dst, src, sz) \
    asm volatile("cp.async.cg.shared.global [%0], [%1], 16, %2;" :: "r"(dst),"l"(src),"r"(sz))
#define CP_COMMIT() asm volatile("cp.async.commit_group;" ::: "memory")
#define CP_WAIT(n)  asm volatile("cp.async.wait_group %0;" :: "n"(n) : "memory")

__device__ __forceinline__ void split1h(float v, __half& h, __half& l) {
    h = __float2half_rn(v);
    l = __float2half_rn(v - __half2float(h));
}
__device__ __forceinline__ float lrelu(float e) { return e > 0.f ? e : LRELU_SLOPE * e; }
__device__ __forceinline__ float sigm(float x)  { return 1.f / (1.f + __expf(-x)); }

// write 8 floats as split fp16 (hi at [c..c+8), lo at [256+c..)) in a 512-wide row
__device__ __forceinline__ void store_split8h(__half* rowp, int c, const float* v) {
    __half2 hp[4], lp[4];
#pragma unroll
    for (int k = 0; k < 4; k++) {
        __half h0, l0, h1, l1;
        split1h(v[2 * k],     h0, l0);
        split1h(v[2 * k + 1], h1, l1);
        hp[k] = __halves2half2(h0, h1);
        lp[k] = __halves2half2(l0, l1);
    }
    *(uint4*)(rowp + c)       = *(uint4*)hp;
    *(uint4*)(rowp + 256 + c) = *(uint4*)lp;
}

// unpack 8 fp16 (as uint4) into floats
__device__ __forceinline__ void half8_to_float(const uint4& v, float* f) {
    const __half2* hh = (const __half2*)&v;
#pragma unroll
    for (int k = 0; k < 4; k++) {
        float2 p = __half22float2(hh[k]);
        f[2 * k] = p.x; f[2 * k + 1] = p.y;
    }
}

// ---------------- CSR build -------------------------------------------------------
__global__ void k_zero_deg() {
    int i = blockIdx.x * blockDim.x + threadIdx.x;
    if (i < NNODE) g_deg[i] = 0;
}
__global__ void k_count(const int* __restrict__ ei) {
    int e = blockIdx.x * blockDim.x + threadIdx.x;
    if (e >= NE_TOT) return;
    int d = (e < NEDGE) ? ei[NEDGE + e] : (e - NEDGE);
    atomicAdd(&g_deg[d], 1);
}
__global__ void k_scan1() {
    __shared__ int sh[1024];
    int b = blockIdx.x, t = threadIdx.x;
    int i = b * 1024 + t;
    int v = (i < NNODE) ? g_deg[i] : 0;
    sh[t] = v;
    __syncthreads();
#pragma unroll
    for (int off = 1; off < 1024; off <<= 1) {
        int u = (t >= off) ? sh[t - off] : 0;
        __syncthreads();
        sh[t] += u;
        __syncthreads();
    }
    if (i < NNODE) g_rowptr[i] = sh[t] - v;
    if (t == 1023) g_bsum[b] = sh[1023];
}
__global__ void k_scan2(int nsb) {
    __shared__ int sh[128];
    int t = threadIdx.x;
    int v = (t < nsb) ? g_bsum[t] : 0;
    sh[t] = v;
    __syncthreads();
#pragma unroll
    for (int off = 1; off < 128; off <<= 1) {
        int u = (t >= off) ? sh[t - off] : 0;
        __syncthreads();
        sh[t] += u;
        __syncthreads();
    }
    g_boff[t] = sh[t] - v;
}
__global__ void k_scan3() {
    int i = blockIdx.x * blockDim.x + threadIdx.x;
    if (i >= NNODE) return;
    int r = g_rowptr[i] + g_boff[i >> 10];
    g_rowptr[i] = r;
    g_cursor[i] = r;
    if (i == 0) g_rowptr[NNODE] = NE_TOT;
}
__global__ void k_fill(const int* __restrict__ ei) {
    int e = blockIdx.x * blockDim.x + threadIdx.x;
    if (e >= NE_TOT) return;
    int s, d;
    if (e < NEDGE) { s = ei[e]; d = ei[NEDGE + e]; }
    else           { s = e - NEDGE; d = s; }
    int pos = atomicAdd(&g_cursor[d], 1);
    g_colsrc[pos] = s;
}

// ---------------- conversions -----------------------------------------------------
__global__ void k_convX(const float* __restrict__ src) {
    long i = (long)blockIdx.x * blockDim.x + threadIdx.x;
    if (i >= (long)NNODE * 64) return;
    int row = (int)(i >> 6);
    int c = (int)(i & 63) * 4;
    float4 v = *(const float4*)(src + (size_t)row * 256 + c);
    __half h0, h1, h2, h3, l0, l1, l2, l3;
    split1h(v.x, h0, l0); split1h(v.y, h1, l1); split1h(v.z, h2, l2); split1h(v.w, h3, l3);
    __half* p = g_Xs + (size_t)row * 512 + c;
    *(__half2*)(p)       = __halves2half2(h0, h1);
    *(__half2*)(p + 2)   = __halves2half2(h2, h3);
    *(__half2*)(p + 256) = __halves2half2(l0, l1);
    *(__half2*)(p + 258) = __halves2half2(l2, l3);
}

__global__ void k_convW(const float* __restrict__ Win, const float* __restrict__ Wh,
                        const float* __restrict__ Wg,  const float* __restrict__ Wl,
                        const float* __restrict__ Wp) {
    int idx = blockIdx.x * blockDim.x + threadIdx.x;
    if (idx >= WB_ROWS * 256) return;
    int row = idx >> 8;
    int k = idx & 255;
    float v = 0.f;
    if (row < 256) {
        v = Win[k * 256 + row];
    } else if (row < 2560) {
        int t = row - 256;
        int layer = t / 768;
        int r2 = t % 768;
        int mat = r2 >> 8;
        int n = r2 & 255;
        const float* W = (mat == 0 ? Wh : (mat == 1 ? Wg : Wl)) + (size_t)layer * 65536;
        v = W[k * 256 + n];
    } else {
        int n = row - 2560;
        if (n < 64) v = Wp[k * 64 + n];
    }
    g_WB[(size_t)row * 256 + k] = __float2half_rn(v);
}

// ---------------- HMMA fp16 2-term split GEMM + fused attention scores ------------
// C[M, *] = (Ahi + Alo)[M,512] @ B[rows,256]^T ; CTA tile 128x128, warp 32x64,
// 8 K-chunks of 64. For seg==attSeg (the HG segment) the epilogue also computes
// a_src/a_dst: one warp's 64-col span is exactly one head; a quad (lane&3) covers
// all 64 cols of rows gr0/gr1, so two shfl_xor reductions give the head dots.
struct Seg {
    void* out;
    const float* bias1;
    const float* bias2;
    int relu;
    int ncols;   // valid cols (also row stride for fmt 0/2)
    int fmt;     // 0 = fp32 out, 1 = split fp16 out ([row,512] hi|lo), 2 = fp16 out
};

#define KC 64
#define A_BYTES (128 * KC * 2)     // 16KB
#define STAGE_BYTES (2 * A_BYTES)  // A + B = 32KB
#define SMEM_DYN (3 * STAGE_BYTES) // 96KB, 3-stage

__global__ void __launch_bounds__(256, 2)
k_gemm(const __half* __restrict__ A, const __half* __restrict__ Bm,
       int M, int tilesPerSeg, Seg s0, Seg s1, Seg s2,
       const float* __restrict__ attS, const float* __restrict__ attD, int attSeg)
{
    extern __shared__ char smem[];
    uint32_t sb = smem_u32(smem);
    int tid = threadIdx.x;
    int lane = tid & 31, warp = tid >> 5;
    int wm = warp >> 1, wn = warp & 1;
    int mBase = blockIdx.y * 128;
    size_t bRow0 = (size_t)blockIdx.x * 128;

    float acc[2][8][4];
#pragma unroll
    for (int i = 0; i < 2; i++)
#pragma unroll
        for (int j = 0; j < 8; j++)
#pragma unroll
            for (int q = 0; q < 4; q++) acc[i][j][q] = 0.f;

    const uint32_t xm = (uint32_t)((lane & 7) << 4);
    const int rA = wm * 32 + ((lane >> 3) & 1) * 8 + (lane & 7);
    const int kAsel = lane >> 4;
    const int rBoff = ((lane >> 4) << 3) + (lane & 7);
    const int kBsel = (lane >> 3) & 1;

    auto load_chunk = [&](int c, int buf) {
        int ka = (c < 4) ? c * 64 : 256 + (c - 4) * 64;
        int kb = (c & 3) * 64;
        uint32_t aBuf = sb + buf * STAGE_BYTES;
        uint32_t bBuf = aBuf + A_BYTES;
#pragma unroll
        for (int it = 0; it < 4; it++) {
            int slot = tid + it * 256;
            int row = slot >> 3, kc = slot & 7;
            int gr = mBase + row;
            uint32_t off = (uint32_t)(row * 128 + kc * 16);
            uint32_t dst = aBuf + (off ^ ((uint32_t)(row & 7) << 4));
            const __half* src = A + (size_t)gr * 512 + ka + kc * 8;
            int sz = (gr < M) ? 16 : 0;
            CPA16(dst, src, sz);
        }
#pragma unroll
        for (int it = 0; it < 4; it++) {
            int slot = tid + it * 256;
            int row = slot >> 3, kc = slot & 7;
            uint32_t off = (uint32_t)(row * 128 + kc * 16);
            uint32_t dst = bBuf + (off ^ ((uint32_t)(row & 7) << 4));
            const __half* src = Bm + (bRow0 + row) * 256 + kb + kc * 8;
            CPA16(dst, src, 16);
        }
        CP_COMMIT();
    };

    load_chunk(0, 0);
    load_chunk(1, 1);

    for (int c = 0; c < NCH; c++) {
        if (c + 2 < NCH) { load_chunk(c + 2, (c + 2) % 3); CP_WAIT(2); }
        else if (c + 1 < NCH) { CP_WAIT(1); }
        else { CP_WAIT(0); }
        __syncthreads();
        uint32_t aBuf = sb + (c % 3) * STAGE_BYTES;
        uint32_t bBuf = aBuf + A_BYTES;
#pragma unroll
        for (int kk = 0; kk < 4; kk++) {
            uint32_t a[2][4];
#pragma unroll
            for (int mt = 0; mt < 2; mt++) {
                uint32_t off = (uint32_t)((rA + mt * 16) * 128 + (kk * 2 + kAsel) * 16);
                uint32_t ad = aBuf + (off ^ xm);
                LDSM4(a[mt][0], a[mt][1], a[mt][2], a[mt][3], ad);
            }
            uint32_t b[4][4];
#pragma unroll
            for (int nt2 = 0; nt2 < 4; nt2++) {
                int rB = wn * 64 + nt2 * 16 + rBoff;
                uint32_t off = (uint32_t)(rB * 128 + (kk * 2 + kBsel) * 16);
                uint32_t ad = bBuf + (off ^ xm);
                LDSM4(b[nt2][0], b[nt2][1], b[nt2][2], b[nt2][3], ad);
            }
#pragma unroll
            for (int mt = 0; mt < 2; mt++)
#pragma unroll
                for (int nt = 0; nt < 8; nt++) {
                    uint32_t b0 = b[nt >> 1][(nt & 1) * 2];
                    uint32_t b1 = b[nt >> 1][(nt & 1) * 2 + 1];
                    MMA16816(acc[mt][nt], a[mt], b0, b1);
                }
        }
        __syncthreads();
    }

    int seg = blockIdx.x / tilesPerSeg;
    int tileInSeg = blockIdx.x - seg * tilesPerSeg;
    Seg s = (seg == 0) ? s0 : (seg == 1) ? s1 : s2;
    int colSegBase = tileInSeg * 128 + wn * 64;
    int r0 = mBase + wm * 32 + (lane >> 2);
    const bool doAttn = (seg == attSeg);
    float aS[2][2], aD[2][2];   // [mt][row gr0 / gr1]
#pragma unroll
    for (int mt = 0; mt < 2; mt++) {
        aS[mt][0] = aS[mt][1] = 0.f;
        aD[mt][0] = aD[mt][1] = 0.f;
    }

#pragma unroll
    for (int mt = 0; mt < 2; mt++) {
        int gr0 = r0 + mt * 16;
        int gr1 = gr0 + 8;
#pragma unroll
        for (int nt = 0; nt < 8; nt++) {
            int col = colSegBase + nt * 8 + (lane & 3) * 2;
            if (col >= s.ncols) continue;
            float v0 = acc[mt][nt][0], v1 = acc[mt][nt][1];
            float v2 = acc[mt][nt][2], v3 = acc[mt][nt][3];
            if (doAttn) {
                float as0 = attS[col], as1 = attS[col + 1];
                float ad0 = attD[col], ad1 = attD[col + 1];
                aS[mt][0] += v0 * as0 + v1 * as1;
                aS[mt][1] += v2 * as0 + v3 * as1;
                aD[mt][0] += v0 * ad0 + v1 * ad1;
                aD[mt][1] += v2 * ad0 + v3 * ad1;
            }
            if (s.bias1) {
                float b0 = s.bias1[col], b1 = s.bias1[col + 1];
                v0 += b0; v1 += b1; v2 += b0; v3 += b1;
            }
            if (s.bias2) {
                float b0 = s.bias2[col], b1 = s.bias2[col + 1];
                v0 += b0; v1 += b1; v2 += b0; v3 += b1;
            }
            if (s.relu) {
                v0 = fmaxf(v0, 0.f); v1 = fmaxf(v1, 0.f);
                v2 = fmaxf(v2, 0.f); v3 = fmaxf(v3, 0.f);
            }
            if (s.fmt == 0) {
                if (gr0 < M) {
                    float2 p; p.x = v0; p.y = v1;
                    *(float2*)((float*)s.out + (size_t)gr0 * s.ncols + col) = p;
                }
                if (gr1 < M) {
                    float2 p; p.x = v2; p.y = v3;
                    *(float2*)((float*)s.out + (size_t)gr1 * s.ncols + col) = p;
                }
            } else if (s.fmt == 2) {
                if (gr0 < M)
                    *(__half2*)((__half*)s.out + (size_t)gr0 * s.ncols + col) = __floats2half2_rn(v0, v1);
                if (gr1 < M)
                    *(__half2*)((__half*)s.out + (size_t)gr1 * s.ncols + col) = __floats2half2_rn(v2, v3);
            } else {
                if (gr0 < M) {
                    __half* op = (__half*)s.out + (size_t)gr0 * 512;
                    __half h0, l0, h1, l1;
                    split1h(v0, h0, l0); split1h(v1, h1, l1);
                    *(__half2*)(op + col) = __halves2half2(h0, h1);
                    *(__half2*)(op + 256 + col) = __halves2half2(l0, l1);
                }
                if (gr1 < M) {
                    __half* op = (__half*)s.out + (size_t)gr1 * 512;
                    __half h0, l0, h1, l1;
                    split1h(v2, h0, l0); split1h(v3, h1, l1);
                    *(__half2*)(op + col) = __halves2half2(h0, h1);
                    *(__half2*)(op + 256 + col) = __halves2half2(l0, l1);
                }
            }
        }
    }

    if (doAttn) {
        int head = colSegBase >> 6;   // tileInSeg*2 + wn, constant per warp
#pragma unroll
        for (int mt = 0; mt < 2; mt++) {
            float s0 = aS[mt][0], s1v = aS[mt][1];
            float d0 = aD[mt][0], d1 = aD[mt][1];
            s0  += __shfl_xor_sync(0xffffffffu, s0, 1);
            s0  += __shfl_xor_sync(0xffffffffu, s0, 2);
            s1v += __shfl_xor_sync(0xffffffffu, s1v, 1);
            s1v += __shfl_xor_sync(0xffffffffu, s1v, 2);
            d0  += __shfl_xor_sync(0xffffffffu, d0, 1);
            d0  += __shfl_xor_sync(0xffffffffu, d0, 2);
            d1  += __shfl_xor_sync(0xffffffffu, d1, 1);
            d1  += __shfl_xor_sync(0xffffffffu, d1, 2);
            if ((lane & 3) == 0) {
                int gr0 = r0 + mt * 16, gr1 = gr0 + 8;
                if (gr0 < M) { g_ASRC[gr0 * 4 + head] = s0;  g_ADST[gr0 * 4 + head] = d0; }
                if (gr1 < M) { g_ASRC[gr1 * 4 + head] = s1v; g_ADST[gr1 * 4 + head] = d1; }
            }
        }
    }
}

// ---------------- fused GAT + residual + relu + LN + gate -------------------------
__global__ void __launch_bounds__(256)
k_gat(const float* __restrict__ lng, const float* __restrict__ lnb,
      const float* __restrict__ betas, int accumulate, int writeX2, int writeXs)
{
    int warp = blockIdx.x * (blockDim.x >> 5) + (threadIdx.x >> 5);
    int lane = threadIdx.x & 31;
    if (warp >= NNODE) return;
    int n = warp;
    int h = lane >> 3;
    int c = lane * 8;
    int start = g_rowptr[n], end = g_rowptr[n + 1];
    float adst_h = g_ADST[n * 4 + h];

    float acc[8];
#pragma unroll
    for (int k = 0; k < 8; k++) acc[k] = 0.f;
    float den = 0.f;

    int j = start;
    for (; j + 1 < end; j += 2) {
        int sA = g_colsrc[j], sB = g_colsrc[j + 1];
        float asA = __ldg(&g_ASRC[sA * 4 + h]);
        float asB = __ldg(&g_ASRC[sB * 4 + h]);
        uint4 vA = *(const uint4*)(g_HG + (size_t)sA * 256 + c);
        uint4 vB = *(const uint4*)(g_HG + (size_t)sB * 256 + c);
        float wA = __expf(lrelu(asA + adst_h));
        float wB = __expf(lrelu(asB + adst_h));
        den += wA + wB;
        const __half2* hA = (const __half2*)&vA;
        const __half2* hB = (const __half2*)&vB;
#pragma unroll
        for (int k = 0; k < 4; k++) {
            float2 fA = __half22float2(hA[k]);
            float2 fB = __half22float2(hB[k]);
            acc[2 * k]     += wA * fA.x + wB * fB.x;
            acc[2 * k + 1] += wA * fA.y + wB * fB.y;
        }
    }
    if (j < end) {
        int s = g_colsrc[j];
        float as = __ldg(&g_ASRC[s * 4 + h]);
        uint4 v = *(const uint4*)(g_HG + (size_t)s * 256 + c);
        float w = __expf(lrelu(as + adst_h));
        den += w;
        const __half2* hh = (const __half2*)&v;
#pragma unroll
        for (int k = 0; k < 4; k++) {
            float2 f = __half22float2(hh[k]);
            acc[2 * k]     += w * f.x;
            acc[2 * k + 1] += w * f.y;
        }
    }
    float inv = 1.f / den;

    uint4 gv = *(const uint4*)(g_GXL + (size_t)n * DMODEL + c);
    uint4 hv = *(const uint4*)(g_H   + (size_t)n * DMODEL + c);
    float gArr[8], hArr[8];
    half8_to_float(gv, gArr);
    half8_to_float(hv, hArr);
    float xv[8], tv[8];
    float s1 = 0.f, s2 = 0.f;
#pragma unroll
    for (int k = 0; k < 8; k++) {
        xv[k] = fmaxf(acc[k] * inv + gArr[k], 0.f);
        tv[k] = hArr[k] * xv[k];
        s1 += tv[k];
        s2 += tv[k] * tv[k];
    }
#pragma unroll
    for (int off = 16; off >= 1; off >>= 1) {
        s1 += __shfl_xor_sync(0xffffffffu, s1, off);
        s2 += __shfl_xor_sync(0xffffffffu, s2, off);
    }
    float mu  = s1 * (1.f / 256.f);
    float var = s2 * (1.f / 256.f) - mu * mu;
    float rstd = rsqrtf(var + LN_EPS);

    const float4* lg = (const float4*)(lng + c);
    const float4* lb = (const float4*)(lnb + c);
    const float4* bt = (const float4*)(betas + c);
    float4 lg0 = lg[0], lg1 = lg[1];
    float4 lb0 = lb[0], lb1 = lb[1];
    float4 bt0 = bt[0], bt1 = bt[1];
    float lgA[8] = {lg0.x, lg0.y, lg0.z, lg0.w, lg1.x, lg1.y, lg1.z, lg1.w};
    float lbA[8] = {lb0.x, lb0.y, lb0.z, lb0.w, lb1.x, lb1.y, lb1.z, lb1.w};
    float btA[8] = {bt0.x, bt0.y, bt0.z, bt0.w, bt1.x, bt1.y, bt1.z, bt1.w};

    float o[8];
#pragma unroll
    for (int k = 0; k < 8; k++) {
        float b = sigm(btA[k]);
        o[k] = (1.f - b) * ((tv[k] - mu) * rstd * lgA[k] + lbA[k]) + b * xv[k];
    }

    if (writeX2) store_split8h(g_X2 + (size_t)n * 512, c, o);

    float* XL = g_XLOC + (size_t)n * DMODEL + c;
    float xl[8];
    if (accumulate) {
        float4 a0 = *(const float4*)(XL);
        float4 a1 = *(const float4*)(XL + 4);
        float aArr[8] = {a0.x, a0.y, a0.z, a0.w, a1.x, a1.y, a1.z, a1.w};
#pragma unroll
        for (int k = 0; k < 8; k++) xl[k] = aArr[k] + o[k];
    } else {
#pragma unroll
        for (int k = 0; k < 8; k++) xl[k] = o[k];
    }
    *(float4*)(XL)     = make_float4(xl[0], xl[1], xl[2], xl[3]);
    *(float4*)(XL + 4) = make_float4(xl[4], xl[5], xl[6], xl[7]);

    if (writeXs) store_split8h(g_Xs + (size_t)n * 512, c, xl);
}

// ---------------- host ------------------------------------------------------------
extern "C" void kernel_launch(void* const* d_in, const int* in_sizes, int n_in,
                              void* d_out, int out_size)
{
    const float* x       = (const float*)d_in[0];
    const int*   ei      = (const int*)  d_in[1];
    const float* Win     = (const float*)d_in[2];
    const float* b_in    = (const float*)d_in[3];
    const float* Wh      = (const float*)d_in[4];
    const float* bh      = (const float*)d_in[5];
    const float* Wg      = (const float*)d_in[6];
    const float* att_src = (const float*)d_in[7];
    const float* att_dst = (const float*)d_in[8];
    const float* bg      = (const float*)d_in[9];
    const float* Wl      = (const float*)d_in[10];
    const float* bl      = (const float*)d_in[11];
    const float* ln_g    = (const float*)d_in[12];
    const float* ln_b    = (const float*)d_in[13];
    const float* betas   = (const float*)d_in[14];
    const float* Wp      = (const float*)d_in[15];
    const float* bp      = (const float*)d_in[16];
    float* out = (float*)d_out;

    cudaFuncSetAttribute(k_gemm, cudaFuncAttributeMaxDynamicSharedMemorySize, SMEM_DYN);

    __half *pXs, *pX2, *pWB, *pHG, *pH, *pGXL;
    cudaGetSymbolAddress((void**)&pXs,  g_Xs);
    cudaGetSymbolAddress((void**)&pX2,  g_X2);
    cudaGetSymbolAddress((void**)&pWB,  g_WB);
    cudaGetSymbolAddress((void**)&pH,   g_H);
    cudaGetSymbolAddress((void**)&pHG,  g_HG);
    cudaGetSymbolAddress((void**)&pGXL, g_GXL);

    const int MT = (NNODE + 127) / 128;   // 782
    Seg z = {nullptr, nullptr, nullptr, 0, 256, 0};

    // launches 1-3, then launch 4 = X0 GEMM (ncu captures the 4th launch)
    k_convX<<<(NNODE * 64 + 255) / 256, 256>>>(x);                       // 1
    k_convW<<<(WB_ROWS * 256 + 255) / 256, 256>>>(Win, Wh, Wg, Wl, Wp); // 2
    k_zero_deg<<<(NNODE + 255) / 256, 256>>>();                          // 3
    {
        Seg s0 = {pX2, b_in, nullptr, 0, 256, 1};
        k_gemm<<<dim3(2, MT), 256, SMEM_DYN>>>(pXs, pWB, NNODE, 2, s0, z, z,
                                               nullptr, nullptr, -1);    // 4 (profiled)
    }

    // CSR build
    k_count<<<(NE_TOT + 255) / 256, 256>>>(ei);
    const int NSB = (NNODE + 1023) / 1024;
    k_scan1<<<NSB, 1024>>>();
    k_scan2<<<1, 128>>>(NSB);
    k_scan3<<<(NNODE + 255) / 256, 256>>>();
    k_fill<<<(NE_TOT + 255) / 256, 256>>>(ei);

    int warpBlocks = (NNODE + 7) / 8;
    for (int i = 0; i < NLAYER; i++) {
        Seg sH  = {pH,   bh + i * DMODEL, nullptr,         1, 256, 2};
        Seg sHG = {pHG,  nullptr,          nullptr,         0, 256, 2};
        Seg sGX = {pGXL, bl + i * DMODEL, bg + i * DMODEL,  0, 256, 2};
        // attention scores fused into the HG (seg 1) epilogue
        k_gemm<<<dim3(6, MT), 256, SMEM_DYN>>>(pX2, pWB + (size_t)(256 + i * 768) * 256,
                                               NNODE, 2, sH, sHG, sGX,
                                               att_src + i * NHEAD * 64,
                                               att_dst + i * NHEAD * 64, 1);
        int last = (i == NLAYER - 1);
        k_gat<<<warpBlocks, 256>>>(ln_g + i * DMODEL, ln_b + i * DMODEL, betas + i * DMODEL,
                                   i, !last, last);
    }

    // out = XLOC @ Wp + bp (A = split(XLOC) written by last k_gat)
    {
        Seg s0 = {out, bp, nullptr, 0, 64, 0};
        k_gemm<<<dim3(1, MT), 256, SMEM_DYN>>>(pXs, pWB + (size_t)2560 * 256, NNODE, 1, s0, z, z,
                                               nullptr, nullptr, -1);
    }
}

// round 14
// speedup vs baseline: 1.0676x; 1.0330x over previous
#include <cuda_runtime.h>
#include <cuda_bf16.h>
#include <cuda_fp16.h>
#include <math.h>
#include <stdint.h>

#define NNODE 100000
#define NEDGE 1600000
#define NE_TOT (NEDGE + NNODE)
#define DMODEL 256
#define NHEAD 4
#define NLAYER 3
#define NOUTC 64
#define LRELU_SLOPE 0.2f
#define LN_EPS 1e-5f

#define NCH 8               // 8 K-chunks of 64 (K' = 512: Ahi·B + Alo·B)
#define WB_ROWS 2816        // 256 (Win) + 3*768 (Wh|Wg|Wl) + 256 (Wp padded)

// ---------------- scratch ---------------------------------------------------------
__device__ __half g_Xs[(size_t)NNODE * 512];   // staging split fp16 (x input / XLOC)
__device__ __half g_X2[(size_t)NNODE * 512];   // live split fp16 X between layers
__device__ __half g_WB[(size_t)WB_ROWS * 256]; // fp16 transposed weights (hi only)
__device__ __half g_H[(size_t)NNODE * DMODEL];  // fp16 (elementwise use only)
__device__ __half g_HG[(size_t)NNODE * DMODEL]; // fp16: 50MB, L2-resident
__device__ __half g_GXL[(size_t)NNODE * DMODEL];// fp16 (elementwise use only)
__device__ float  g_XLOC[(size_t)NNODE * DMODEL];
__device__ float  g_ASRC[NNODE * NHEAD];
__device__ float  g_ADST[NNODE * NHEAD];
__device__ int    g_deg[NNODE];
__device__ int    g_rowptr[NNODE + 1];
__device__ int    g_cursor[NNODE];
__device__ int    g_colsrc[NE_TOT];
__device__ int    g_bsum[128];
__device__ int    g_boff[128];

// ---------------- asm helpers (sm_80-era features: valid on sm_103 base) ----------
__device__ __forceinline__ uint32_t smem_u32(const void* p) {
    uint32_t a;
    asm("{ .reg .u64 t; cvta.to.shared.u64 t, %1; cvt.u32.u64 %0, t; }" : "=r"(a) : "l"(p));
    return a;
}
#define LDSM4(r0,r1,r2,r3, addr) \
    asm volatile("ldmatrix.sync.aligned.m8n8.x4.shared.b16 {%0,%1,%2,%3}, [%4];" \
        : "=r"(r0),"=r"(r1),"=r"(r2),"=r"(r3) : "r"(addr))
#define MMA16816(d, a, b0, b1) \
    asm volatile("mma.sync.aligned.m16n8k16.row.col.f32.f16.f16.f32 " \
        "{%0,%1,%2,%3},{%4,%5,%6,%7},{%8,%9},{%0,%1,%2,%3};" \
        : "+f"((d)[0]),"+f"((d)[1]),"+f"((d)[2]),"+f"((d)[3]) \
        : "r"((a)[0]),"r"((a)[1]),"r"((a)[2]),"r"((a)[3]),"r"(b0),"r"(b1))
#define CPA16(dst, src, sz) \
    asm volatile("cp.async.cg.shared.global [%0], [%1], 16, %2;" :: "r"(dst),"l"(src),"r"(sz))
#define CP_COMMIT() asm volatile("cp.async.commit_group;" ::: "memory")
#define CP_WAIT(n)  asm volatile("cp.async.wait_group %0;" :: "n"(n) : "memory")

__device__ __forceinline__ void split1h(float v, __half& h, __half& l) {
    h = __float2half_rn(v);
    l = __float2half_rn(v - __half2float(h));
}
__device__ __forceinline__ float lrelu(float e) { return e > 0.f ? e : LRELU_SLOPE * e; }
__device__ __forceinline__ float sigm(float x)  { return 1.f / (1.f + __expf(-x)); }

// write 8 floats as split fp16 (hi at [c..c+8), lo at [256+c..)) in a 512-wide row
__device__ __forceinline__ void store_split8h(__half* rowp, int c, const float* v) {
    __half2 hp[4], lp[4];
#pragma unroll
    for (int k = 0; k < 4; k++) {
        __half h0, l0, h1, l1;
        split1h(v[2 * k],     h0, l0);
        split1h(v[2 * k + 1], h1, l1);
        hp[k] = __halves2half2(h0, h1);
        lp[k] = __halves2half2(l0, l1);
    }
    *(uint4*)(rowp + c)       = *(uint4*)hp;
    *(uint4*)(rowp + 256 + c) = *(uint4*)lp;
}

// unpack 8 fp16 (as uint4) into floats
__device__ __forceinline__ void half8_to_float(const uint4& v, float* f) {
    const __half2* hh = (const __half2*)&v;
#pragma unroll
    for (int k = 0; k < 4; k++) {
        float2 p = __half22float2(hh[k]);
        f[2 * k] = p.x; f[2 * k + 1] = p.y;
    }
}

// ---------------- CSR build -------------------------------------------------------
__global__ void k_zero_deg() {
    int i = blockIdx.x * blockDim.x + threadIdx.x;
    if (i < NNODE) g_deg[i] = 0;
}
__global__ void k_count(const int* __restrict__ ei) {
    int e = blockIdx.x * blockDim.x + threadIdx.x;
    if (e >= NE_TOT) return;
    int d = (e < NEDGE) ? ei[NEDGE + e] : (e - NEDGE);
    atomicAdd(&g_deg[d], 1);
}
__global__ void k_scan1() {
    __shared__ int sh[1024];
    int b = blockIdx.x, t = threadIdx.x;
    int i = b * 1024 + t;
    int v = (i < NNODE) ? g_deg[i] : 0;
    sh[t] = v;
    __syncthreads();
#pragma unroll
    for (int off = 1; off < 1024; off <<= 1) {
        int u = (t >= off) ? sh[t - off] : 0;
        __syncthreads();
        sh[t] += u;
        __syncthreads();
    }
    if (i < NNODE) g_rowptr[i] = sh[t] - v;
    if (t == 1023) g_bsum[b] = sh[1023];
}
__global__ void k_scan2(int nsb) {
    __shared__ int sh[128];
    int t = threadIdx.x;
    int v = (t < nsb) ? g_bsum[t] : 0;
    sh[t] = v;
    __syncthreads();
#pragma unroll
    for (int off = 1; off < 128; off <<= 1) {
        int u = (t >= off) ? sh[t - off] : 0;
        __syncthreads();
        sh[t] += u;
        __syncthreads();
    }
    g_boff[t] = sh[t] - v;
}
__global__ void k_scan3() {
    int i = blockIdx.x * blockDim.x + threadIdx.x;
    if (i >= NNODE) return;
    int r = g_rowptr[i] + g_boff[i >> 10];
    g_rowptr[i] = r;
    g_cursor[i] = r;
    if (i == 0) g_rowptr[NNODE] = NE_TOT;
}
__global__ void k_fill(const int* __restrict__ ei) {
    int e = blockIdx.x * blockDim.x + threadIdx.x;
    if (e >= NE_TOT) return;
    int s, d;
    if (e < NEDGE) { s = ei[e]; d = ei[NEDGE + e]; }
    else           { s = e - NEDGE; d = s; }
    int pos = atomicAdd(&g_cursor[d], 1);
    g_colsrc[pos] = s;
}

// ---------------- conversions -----------------------------------------------------
__global__ void k_convX(const float* __restrict__ src) {
    long i = (long)blockIdx.x * blockDim.x + threadIdx.x;
    if (i >= (long)NNODE * 64) return;
    int row = (int)(i >> 6);
    int c = (int)(i & 63) * 4;
    float4 v = *(const float4*)(src + (size_t)row * 256 + c);
    __half h0, h1, h2, h3, l0, l1, l2, l3;
    split1h(v.x, h0, l0); split1h(v.y, h1, l1); split1h(v.z, h2, l2); split1h(v.w, h3, l3);
    __half* p = g_Xs + (size_t)row * 512 + c;
    *(__half2*)(p)       = __halves2half2(h0, h1);
    *(__half2*)(p + 2)   = __halves2half2(h2, h3);
    *(__half2*)(p + 256) = __halves2half2(l0, l1);
    *(__half2*)(p + 258) = __halves2half2(l2, l3);
}

__global__ void k_convW(const float* __restrict__ Win, const float* __restrict__ Wh,
                        const float* __restrict__ Wg,  const float* __restrict__ Wl,
                        const float* __restrict__ Wp) {
    int idx = blockIdx.x * blockDim.x + threadIdx.x;
    if (idx >= WB_ROWS * 256) return;
    int row = idx >> 8;
    int k = idx & 255;
    float v = 0.f;
    if (row < 256) {
        v = Win[k * 256 + row];
    } else if (row < 2560) {
        int t = row - 256;
        int layer = t / 768;
        int r2 = t % 768;
        int mat = r2 >> 8;
        int n = r2 & 255;
        const float* W = (mat == 0 ? Wh : (mat == 1 ? Wg : Wl)) + (size_t)layer * 65536;
        v = W[k * 256 + n];
    } else {
        int n = row - 2560;
        if (n < 64) v = Wp[k * 64 + n];
    }
    g_WB[(size_t)row * 256 + k] = __float2half_rn(v);
}

// ---------------- HMMA fp16 2-term split GEMM + fused attention scores ------------
// C[M, *] = (Ahi + Alo)[M,512] @ B[rows,256]^T ; CTA tile 128x128, warp 32x64,
// up to 8 K-chunks of 64. Segment 0 may run only nch0 chunks (nch0=4 -> A-hi only,
// used for the H segment whose output only feeds elementwise h*x before LN).
// For seg==attSeg the epilogue also computes a_src/a_dst per head via quad shfl.
struct Seg {
    void* out;
    const float* bias1;
    const float* bias2;
    int relu;
    int ncols;   // valid cols (also row stride for fmt 0/2)
    int fmt;     // 0 = fp32 out, 1 = split fp16 out ([row,512] hi|lo), 2 = fp16 out
};

#define KC 64
#define A_BYTES (128 * KC * 2)     // 16KB
#define STAGE_BYTES (2 * A_BYTES)  // A + B = 32KB
#define SMEM_DYN (3 * STAGE_BYTES) // 96KB, 3-stage

__global__ void __launch_bounds__(256, 2)
k_gemm(const __half* __restrict__ A, const __half* __restrict__ Bm,
       int M, int tilesPerSeg, Seg s0, Seg s1, Seg s2,
       const float* __restrict__ attS, const float* __restrict__ attD, int attSeg,
       int nch0)
{
    extern __shared__ char smem[];
    uint32_t sb = smem_u32(smem);
    int tid = threadIdx.x;
    int lane = tid & 31, warp = tid >> 5;
    int wm = warp >> 1, wn = warp & 1;
    int mBase = blockIdx.y * 128;
    size_t bRow0 = (size_t)blockIdx.x * 128;
    int seg = blockIdx.x / tilesPerSeg;
    const int nch = (seg == 0) ? nch0 : NCH;

    float acc[2][8][4];
#pragma unroll
    for (int i = 0; i < 2; i++)
#pragma unroll
        for (int j = 0; j < 8; j++)
#pragma unroll
            for (int q = 0; q < 4; q++) acc[i][j][q] = 0.f;

    const uint32_t xm = (uint32_t)((lane & 7) << 4);
    const int rA = wm * 32 + ((lane >> 3) & 1) * 8 + (lane & 7);
    const int kAsel = lane >> 4;
    const int rBoff = ((lane >> 4) << 3) + (lane & 7);
    const int kBsel = (lane >> 3) & 1;

    auto load_chunk = [&](int c, int buf) {
        int ka = (c < 4) ? c * 64 : 256 + (c - 4) * 64;
        int kb = (c & 3) * 64;
        uint32_t aBuf = sb + buf * STAGE_BYTES;
        uint32_t bBuf = aBuf + A_BYTES;
#pragma unroll
        for (int it = 0; it < 4; it++) {
            int slot = tid + it * 256;
            int row = slot >> 3, kc = slot & 7;
            int gr = mBase + row;
            uint32_t off = (uint32_t)(row * 128 + kc * 16);
            uint32_t dst = aBuf + (off ^ ((uint32_t)(row & 7) << 4));
            const __half* src = A + (size_t)gr * 512 + ka + kc * 8;
            int sz = (gr < M) ? 16 : 0;
            CPA16(dst, src, sz);
        }
#pragma unroll
        for (int it = 0; it < 4; it++) {
            int slot = tid + it * 256;
            int row = slot >> 3, kc = slot & 7;
            uint32_t off = (uint32_t)(row * 128 + kc * 16);
            uint32_t dst = bBuf + (off ^ ((uint32_t)(row & 7) << 4));
            const __half* src = Bm + (bRow0 + row) * 256 + kb + kc * 8;
            CPA16(dst, src, 16);
        }
        CP_COMMIT();
    };

    load_chunk(0, 0);
    load_chunk(1, 1);

    for (int c = 0; c < nch; c++) {
        if (c + 2 < nch) { load_chunk(c + 2, (c + 2) % 3); CP_WAIT(2); }
        else if (c + 1 < nch) { CP_WAIT(1); }
        else { CP_WAIT(0); }
        __syncthreads();
        uint32_t aBuf = sb + (c % 3) * STAGE_BYTES;
        uint32_t bBuf = aBuf + A_BYTES;
#pragma unroll
        for (int kk = 0; kk < 4; kk++) {
            uint32_t a[2][4];
#pragma unroll
            for (int mt = 0; mt < 2; mt++) {
                uint32_t off = (uint32_t)((rA + mt * 16) * 128 + (kk * 2 + kAsel) * 16);
                uint32_t ad = aBuf + (off ^ xm);
                LDSM4(a[mt][0], a[mt][1], a[mt][2], a[mt][3], ad);
            }
            uint32_t b[4][4];
#pragma unroll
            for (int nt2 = 0; nt2 < 4; nt2++) {
                int rB = wn * 64 + nt2 * 16 + rBoff;
                uint32_t off = (uint32_t)(rB * 128 + (kk * 2 + kBsel) * 16);
                uint32_t ad = bBuf + (off ^ xm);
                LDSM4(b[nt2][0], b[nt2][1], b[nt2][2], b[nt2][3], ad);
            }
#pragma unroll
            for (int mt = 0; mt < 2; mt++)
#pragma unroll
                for (int nt = 0; nt < 8; nt++) {
                    uint32_t b0 = b[nt >> 1][(nt & 1) * 2];
                    uint32_t b1 = b[nt >> 1][(nt & 1) * 2 + 1];
                    MMA16816(acc[mt][nt], a[mt], b0, b1);
                }
        }
        __syncthreads();
    }

    int tileInSeg = blockIdx.x - seg * tilesPerSeg;
    Seg s = (seg == 0) ? s0 : (seg == 1) ? s1 : s2;
    int colSegBase = tileInSeg * 128 + wn * 64;
    int r0 = mBase + wm * 32 + (lane >> 2);
    const bool doAttn = (seg == attSeg);
    float aS[2][2], aD[2][2];   // [mt][row gr0 / gr1]
#pragma unroll
    for (int mt = 0; mt < 2; mt++) {
        aS[mt][0] = aS[mt][1] = 0.f;
        aD[mt][0] = aD[mt][1] = 0.f;
    }

#pragma unroll
    for (int mt = 0; mt < 2; mt++) {
        int gr0 = r0 + mt * 16;
        int gr1 = gr0 + 8;
#pragma unroll
        for (int nt = 0; nt < 8; nt++) {
            int col = colSegBase + nt * 8 + (lane & 3) * 2;
            if (col >= s.ncols) continue;
            float v0 = acc[mt][nt][0], v1 = acc[mt][nt][1];
            float v2 = acc[mt][nt][2], v3 = acc[mt][nt][3];
            if (doAttn) {
                float as0 = attS[col], as1 = attS[col + 1];
                float ad0 = attD[col], ad1 = attD[col + 1];
                aS[mt][0] += v0 * as0 + v1 * as1;
                aS[mt][1] += v2 * as0 + v3 * as1;
                aD[mt][0] += v0 * ad0 + v1 * ad1;
                aD[mt][1] += v2 * ad0 + v3 * ad1;
            }
            if (s.bias1) {
                float b0 = s.bias1[col], b1 = s.bias1[col + 1];
                v0 += b0; v1 += b1; v2 += b0; v3 += b1;
            }
            if (s.bias2) {
                float b0 = s.bias2[col], b1 = s.bias2[col + 1];
                v0 += b0; v1 += b1; v2 += b0; v3 += b1;
            }
            if (s.relu) {
                v0 = fmaxf(v0, 0.f); v1 = fmaxf(v1, 0.f);
                v2 = fmaxf(v2, 0.f); v3 = fmaxf(v3, 0.f);
            }
            if (s.fmt == 0) {
                if (gr0 < M) {
                    float2 p; p.x = v0; p.y = v1;
                    *(float2*)((float*)s.out + (size_t)gr0 * s.ncols + col) = p;
                }
                if (gr1 < M) {
                    float2 p; p.x = v2; p.y = v3;
                    *(float2*)((float*)s.out + (size_t)gr1 * s.ncols + col) = p;
                }
            } else if (s.fmt == 2) {
                if (gr0 < M)
                    *(__half2*)((__half*)s.out + (size_t)gr0 * s.ncols + col) = __floats2half2_rn(v0, v1);
                if (gr1 < M)
                    *(__half2*)((__half*)s.out + (size_t)gr1 * s.ncols + col) = __floats2half2_rn(v2, v3);
            } else {
                if (gr0 < M) {
                    __half* op = (__half*)s.out + (size_t)gr0 * 512;
                    __half h0, l0, h1, l1;
                    split1h(v0, h0, l0); split1h(v1, h1, l1);
                    *(__half2*)(op + col) = __halves2half2(h0, h1);
                    *(__half2*)(op + 256 + col) = __halves2half2(l0, l1);
                }
                if (gr1 < M) {
                    __half* op = (__half*)s.out + (size_t)gr1 * 512;
                    __half h0, l0, h1, l1;
                    split1h(v2, h0, l0); split1h(v3, h1, l1);
                    *(__half2*)(op + col) = __halves2half2(h0, h1);
                    *(__half2*)(op + 256 + col) = __halves2half2(l0, l1);
                }
            }
        }
    }

    if (doAttn) {
        int head = colSegBase >> 6;   // tileInSeg*2 + wn, constant per warp
#pragma unroll
        for (int mt = 0; mt < 2; mt++) {
            float s0 = aS[mt][0], s1v = aS[mt][1];
            float d0 = aD[mt][0], d1 = aD[mt][1];
            s0  += __shfl_xor_sync(0xffffffffu, s0, 1);
            s0  += __shfl_xor_sync(0xffffffffu, s0, 2);
            s1v += __shfl_xor_sync(0xffffffffu, s1v, 1);
            s1v += __shfl_xor_sync(0xffffffffu, s1v, 2);
            d0  += __shfl_xor_sync(0xffffffffu, d0, 1);
            d0  += __shfl_xor_sync(0xffffffffu, d0, 2);
            d1  += __shfl_xor_sync(0xffffffffu, d1, 1);
            d1  += __shfl_xor_sync(0xffffffffu, d1, 2);
            if ((lane & 3) == 0) {
                int gr0 = r0 + mt * 16, gr1 = gr0 + 8;
                if (gr0 < M) { g_ASRC[gr0 * 4 + head] = s0;  g_ADST[gr0 * 4 + head] = d0; }
                if (gr1 < M) { g_ASRC[gr1 * 4 + head] = s1v; g_ADST[gr1 * 4 + head] = d1; }
            }
        }
    }
}

// ---------------- fused GAT + residual + relu + LN + gate -------------------------
__global__ void __launch_bounds__(256)
k_gat(const float* __restrict__ lng, const float* __restrict__ lnb,
      const float* __restrict__ betas, int accumulate, int writeX2, int writeXs)
{
    int warp = blockIdx.x * (blockDim.x >> 5) + (threadIdx.x >> 5);
    int lane = threadIdx.x & 31;
    if (warp >= NNODE) return;
    int n = warp;
    int h = lane >> 3;
    int c = lane * 8;
    int start = g_rowptr[n], end = g_rowptr[n + 1];
    float adst_h = g_ADST[n * 4 + h];

    float acc[8];
#pragma unroll
    for (int k = 0; k < 8; k++) acc[k] = 0.f;
    float den = 0.f;

    int j = start;
    for (; j + 1 < end; j += 2) {
        int sA = g_colsrc[j], sB = g_colsrc[j + 1];
        float asA = __ldg(&g_ASRC[sA * 4 + h]);
        float asB = __ldg(&g_ASRC[sB * 4 + h]);
        uint4 vA = *(const uint4*)(g_HG + (size_t)sA * 256 + c);
        uint4 vB = *(const uint4*)(g_HG + (size_t)sB * 256 + c);
        float wA = __expf(lrelu(asA + adst_h));
        float wB = __expf(lrelu(asB + adst_h));
        den += wA + wB;
        const __half2* hA = (const __half2*)&vA;
        const __half2* hB = (const __half2*)&vB;
#pragma unroll
        for (int k = 0; k < 4; k++) {
            float2 fA = __half22float2(hA[k]);
            float2 fB = __half22float2(hB[k]);
            acc[2 * k]     += wA * fA.x + wB * fB.x;
            acc[2 * k + 1] += wA * fA.y + wB * fB.y;
        }
    }
    if (j < end) {
        int s = g_colsrc[j];
        float as = __ldg(&g_ASRC[s * 4 + h]);
        uint4 v = *(const uint4*)(g_HG + (size_t)s * 256 + c);
        float w = __expf(lrelu(as + adst_h));
        den += w;
        const __half2* hh = (const __half2*)&v;
#pragma unroll
        for (int k = 0; k < 4; k++) {
            float2 f = __half22float2(hh[k]);
            acc[2 * k]     += w * f.x;
            acc[2 * k + 1] += w * f.y;
        }
    }
    float inv = 1.f / den;

    uint4 gv = *(const uint4*)(g_GXL + (size_t)n * DMODEL + c);
    uint4 hv = *(const uint4*)(g_H   + (size_t)n * DMODEL + c);
    float gArr[8], hArr[8];
    half8_to_float(gv, gArr);
    half8_to_float(hv, hArr);
    float xv[8], tv[8];
    float s1 = 0.f, s2 = 0.f;
#pragma unroll
    for (int k = 0; k < 8; k++) {
        xv[k] = fmaxf(acc[k] * inv + gArr[k], 0.f);
        tv[k] = hArr[k] * xv[k];
        s1 += tv[k];
        s2 += tv[k] * tv[k];
    }
#pragma unroll
    for (int off = 16; off >= 1; off >>= 1) {
        s1 += __shfl_xor_sync(0xffffffffu, s1, off);
        s2 += __shfl_xor_sync(0xffffffffu, s2, off);
    }
    float mu  = s1 * (1.f / 256.f);
    float var = s2 * (1.f / 256.f) - mu * mu;
    float rstd = rsqrtf(var + LN_EPS);

    const float4* lg = (const float4*)(lng + c);
    const float4* lb = (const float4*)(lnb + c);
    const float4* bt = (const float4*)(betas + c);
    float4 lg0 = lg[0], lg1 = lg[1];
    float4 lb0 = lb[0], lb1 = lb[1];
    float4 bt0 = bt[0], bt1 = bt[1];
    float lgA[8] = {lg0.x, lg0.y, lg0.z, lg0.w, lg1.x, lg1.y, lg1.z, lg1.w};
    float lbA[8] = {lb0.x, lb0.y, lb0.z, lb0.w, lb1.x, lb1.y, lb1.z, lb1.w};
    float btA[8] = {bt0.x, bt0.y, bt0.z, bt0.w, bt1.x, bt1.y, bt1.z, bt1.w};

    float o[8];
#pragma unroll
    for (int k = 0; k < 8; k++) {
        float b = sigm(btA[k]);
        o[k] = (1.f - b) * ((tv[k] - mu) * rstd * lgA[k] + lbA[k]) + b * xv[k];
    }

    if (writeX2) store_split8h(g_X2 + (size_t)n * 512, c, o);

    float* XL = g_XLOC + (size_t)n * DMODEL + c;
    float xl[8];
    if (accumulate) {
        float4 a0 = *(const float4*)(XL);
        float4 a1 = *(const float4*)(XL + 4);
        float aArr[8] = {a0.x, a0.y, a0.z, a0.w, a1.x, a1.y, a1.z, a1.w};
#pragma unroll
        for (int k = 0; k < 8; k++) xl[k] = aArr[k] + o[k];
    } else {
#pragma unroll
        for (int k = 0; k < 8; k++) xl[k] = o[k];
    }
    *(float4*)(XL)     = make_float4(xl[0], xl[1], xl[2], xl[3]);
    *(float4*)(XL + 4) = make_float4(xl[4], xl[5], xl[6], xl[7]);

    if (writeXs) store_split8h(g_Xs + (size_t)n * 512, c, xl);
}

// ---------------- host ------------------------------------------------------------
extern "C" void kernel_launch(void* const* d_in, const int* in_sizes, int n_in,
                              void* d_out, int out_size)
{
    const float* x       = (const float*)d_in[0];
    const int*   ei      = (const int*)  d_in[1];
    const float* Win     = (const float*)d_in[2];
    const float* b_in    = (const float*)d_in[3];
    const float* Wh      = (const float*)d_in[4];
    const float* bh      = (const float*)d_in[5];
    const float* Wg      = (const float*)d_in[6];
    const float* att_src = (const float*)d_in[7];
    const float* att_dst = (const float*)d_in[8];
    const float* bg      = (const float*)d_in[9];
    const float* Wl      = (const float*)d_in[10];
    const float* bl      = (const float*)d_in[11];
    const float* ln_g    = (const float*)d_in[12];
    const float* ln_b    = (const float*)d_in[13];
    const float* betas   = (const float*)d_in[14];
    const float* Wp      = (const float*)d_in[15];
    const float* bp      = (const float*)d_in[16];
    float* out = (float*)d_out;

    cudaFuncSetAttribute(k_gemm, cudaFuncAttributeMaxDynamicSharedMemorySize, SMEM_DYN);

    __half *pXs, *pX2, *pWB, *pHG, *pH, *pGXL;
    cudaGetSymbolAddress((void**)&pXs,  g_Xs);
    cudaGetSymbolAddress((void**)&pX2,  g_X2);
    cudaGetSymbolAddress((void**)&pWB,  g_WB);
    cudaGetSymbolAddress((void**)&pH,   g_H);
    cudaGetSymbolAddress((void**)&pHG,  g_HG);
    cudaGetSymbolAddress((void**)&pGXL, g_GXL);

    const int MT = (NNODE + 127) / 128;   // 782
    Seg z = {nullptr, nullptr, nullptr, 0, 256, 0};

    // launches 1-3, then launch 4 = X0 GEMM (ncu captures the 4th launch)
    k_convX<<<(NNODE * 64 + 255) / 256, 256>>>(x);                       // 1
    k_convW<<<(WB_ROWS * 256 + 255) / 256, 256>>>(Win, Wh, Wg, Wl, Wp); // 2
    k_zero_deg<<<(NNODE + 255) / 256, 256>>>();                          // 3
    {
        Seg s0 = {pX2, b_in, nullptr, 0, 256, 1};
        k_gemm<<<dim3(2, MT), 256, SMEM_DYN>>>(pXs, pWB, NNODE, 2, s0, z, z,
                                               nullptr, nullptr, -1, NCH);  // 4 (profiled)
    }

    // CSR build
    k_count<<<(NE_TOT + 255) / 256, 256>>>(ei);
    const int NSB = (NNODE + 1023) / 1024;
    k_scan1<<<NSB, 1024>>>();
    k_scan2<<<1, 128>>>(NSB);
    k_scan3<<<(NNODE + 255) / 256, 256>>>();
    k_fill<<<(NE_TOT + 255) / 256, 256>>>(ei);

    int warpBlocks = (NNODE + 7) / 8;
    for (int i = 0; i < NLAYER; i++) {
        Seg sH  = {pH,   bh + i * DMODEL, nullptr,         1, 256, 2};
        Seg sHG = {pHG,  nullptr,          nullptr,         0, 256, 2};
        Seg sGX = {pGXL, bl + i * DMODEL, bg + i * DMODEL,  0, 256, 2};
        // attention scores fused into the HG (seg 1) epilogue;
        // H segment (seg 0) runs A-hi only (nch0 = 4): H feeds only h*x -> LN.
        k_gemm<<<dim3(6, MT), 256, SMEM_DYN>>>(pX2, pWB + (size_t)(256 + i * 768) * 256,
                                               NNODE, 2, sH, sHG, sGX,
                                               att_src + i * NHEAD * 64,
                                               att_dst + i * NHEAD * 64, 1, 4);
        int last = (i == NLAYER - 1);
        k_gat<<<warpBlocks, 256>>>(ln_g + i * DMODEL, ln_b + i * DMODEL, betas + i * DMODEL,
                                   i, !last, last);
    }

    // out = XLOC @ Wp + bp (A = split(XLOC) written by last k_gat)
    {
        Seg s0 = {out, bp, nullptr, 0, 64, 0};
        k_gemm<<<dim3(1, MT), 256, SMEM_DYN>>>(pXs, pWB + (size_t)2560 * 256, NNODE, 1, s0, z, z,
                                               nullptr, nullptr, -1, NCH);
    }
}

// round 15
// speedup vs baseline: 1.0726x; 1.0047x over previous
#include <cuda_runtime.h>
#include <cuda_bf16.h>
#include <cuda_fp16.h>
#include <math.h>
#include <stdint.h>

#define NNODE 100000
#define NEDGE 1600000
#define NE_TOT (NEDGE + NNODE)
#define DMODEL 256
#define NHEAD 4
#define NLAYER 3
#define NOUTC 64
#define LRELU_SLOPE 0.2f
#define LN_EPS 1e-5f

#define NCH 8               // 8 K-chunks of 64 (K' = 512: Ahi·B + Alo·B)
#define WB_ROWS 2816        // 256 (Win) + 3*768 (Wh|Wg|Wl) + 256 (Wp padded)

// ---------------- scratch ---------------------------------------------------------
__device__ __half g_Xs[(size_t)NNODE * 512];   // staging split fp16 (x input / XLOC)
__device__ __half g_X2[(size_t)NNODE * 512];   // live split fp16 X between layers
__device__ __half g_WB[(size_t)WB_ROWS * 256]; // fp16 transposed weights (hi only)
__device__ __half g_H[(size_t)NNODE * DMODEL];  // fp16 (elementwise use only)
__device__ __half g_HG[(size_t)NNODE * DMODEL]; // fp16: 50MB, L2-resident
__device__ __half g_GXL[(size_t)NNODE * DMODEL];// fp16 (elementwise use only)
__device__ float  g_XLOC[(size_t)NNODE * DMODEL];
__device__ float  g_ASRC[NNODE * NHEAD];
__device__ float  g_ADST[NNODE * NHEAD];
__device__ int    g_deg[NNODE];
__device__ int    g_rowptr[NNODE + 1];
__device__ int    g_cursor[NNODE];
__device__ int    g_colsrc[NE_TOT];
__device__ int    g_bsum[128];
__device__ int    g_boff[128];

// ---------------- asm helpers (sm_80-era features: valid on sm_103 base) ----------
__device__ __forceinline__ uint32_t smem_u32(const void* p) {
    uint32_t a;
    asm("{ .reg .u64 t; cvta.to.shared.u64 t, %1; cvt.u32.u64 %0, t; }" : "=r"(a) : "l"(p));
    return a;
}
#define LDSM4(r0,r1,r2,r3, addr) \
    asm volatile("ldmatrix.sync.aligned.m8n8.x4.shared.b16 {%0,%1,%2,%3}, [%4];" \
        : "=r"(r0),"=r"(r1),"=r"(r2),"=r"(r3) : "r"(addr))
#define MMA16816(d, a, b0, b1) \
    asm volatile("mma.sync.aligned.m16n8k16.row.col.f32.f16.f16.f32 " \
        "{%0,%1,%2,%3},{%4,%5,%6,%7},{%8,%9},{%0,%1,%2,%3};" \
        : "+f"((d)[0]),"+f"((d)[1]),"+f"((d)[2]),"+f"((d)[3]) \
        : "r"((a)[0]),"r"((a)[1]),"r"((a)[2]),"r"((a)[3]),"r"(b0),"r"(b1))
#define CPA16(dst, src, sz) \
    asm volatile("cp.async.cg.shared.global [%0], [%1], 16, %2;" :: "r"(dst),"l"(src),"r"(sz))
#define CP_COMMIT() asm volatile("cp.async.commit_group;" ::: "memory")
#define CP_WAIT(n)  asm volatile("cp.async.wait_group %0;" :: "n"(n) : "memory")

__device__ __forceinline__ void split1h(float v, __half& h, __half& l) {
    h = __float2half_rn(v);
    l = __float2half_rn(v - __half2float(h));
}
__device__ __forceinline__ float lrelu(float e) { return e > 0.f ? e : LRELU_SLOPE * e; }
__device__ __forceinline__ float sigm(float x)  { return 1.f / (1.f + __expf(-x)); }

// write 8 floats as split fp16 (hi at [c..c+8), lo at [256+c..)) in a 512-wide row
__device__ __forceinline__ void store_split8h(__half* rowp, int c, const float* v) {
    __half2 hp[4], lp[4];
#pragma unroll
    for (int k = 0; k < 4; k++) {
        __half h0, l0, h1, l1;
        split1h(v[2 * k],     h0, l0);
        split1h(v[2 * k + 1], h1, l1);
        hp[k] = __halves2half2(h0, h1);
        lp[k] = __halves2half2(l0, l1);
    }
    *(uint4*)(rowp + c)       = *(uint4*)hp;
    *(uint4*)(rowp + 256 + c) = *(uint4*)lp;
}

// unpack 8 fp16 (as uint4) into floats
__device__ __forceinline__ void half8_to_float(const uint4& v, float* f) {
    const __half2* hh = (const __half2*)&v;
#pragma unroll
    for (int k = 0; k < 4; k++) {
        float2 p = __half22float2(hh[k]);
        f[2 * k] = p.x; f[2 * k + 1] = p.y;
    }
}

// ---------------- CSR build -------------------------------------------------------
__global__ void k_zero_deg() {
    int i = blockIdx.x * blockDim.x + threadIdx.x;
    if (i < NNODE) g_deg[i] = 0;
}
__global__ void k_count(const int* __restrict__ ei) {
    int e = blockIdx.x * blockDim.x + threadIdx.x;
    if (e >= NE_TOT) return;
    int d = (e < NEDGE) ? ei[NEDGE + e] : (e - NEDGE);
    atomicAdd(&g_deg[d], 1);
}
__global__ void k_scan1() {
    __shared__ int sh[1024];
    int b = blockIdx.x, t = threadIdx.x;
    int i = b * 1024 + t;
    int v = (i < NNODE) ? g_deg[i] : 0;
    sh[t] = v;
    __syncthreads();
#pragma unroll
    for (int off = 1; off < 1024; off <<= 1) {
        int u = (t >= off) ? sh[t - off] : 0;
        __syncthreads();
        sh[t] += u;
        __syncthreads();
    }
    if (i < NNODE) g_rowptr[i] = sh[t] - v;
    if (t == 1023) g_bsum[b] = sh[1023];
}
__global__ void k_scan2(int nsb) {
    __shared__ int sh[128];
    int t = threadIdx.x;
    int v = (t < nsb) ? g_bsum[t] : 0;
    sh[t] = v;
    __syncthreads();
#pragma unroll
    for (int off = 1; off < 128; off <<= 1) {
        int u = (t >= off) ? sh[t - off] : 0;
        __syncthreads();
        sh[t] += u;
        __syncthreads();
    }
    g_boff[t] = sh[t] - v;
}
__global__ void k_scan3() {
    int i = blockIdx.x * blockDim.x + threadIdx.x;
    if (i >= NNODE) return;
    int r = g_rowptr[i] + g_boff[i >> 10];
    g_rowptr[i] = r;
    g_cursor[i] = r;
    if (i == 0) g_rowptr[NNODE] = NE_TOT;
}
__global__ void k_fill(const int* __restrict__ ei) {
    int e = blockIdx.x * blockDim.x + threadIdx.x;
    if (e >= NE_TOT) return;
    int s, d;
    if (e < NEDGE) { s = ei[e]; d = ei[NEDGE + e]; }
    else           { s = e - NEDGE; d = s; }
    int pos = atomicAdd(&g_cursor[d], 1);
    g_colsrc[pos] = s;
}

// ---------------- conversions -----------------------------------------------------
__global__ void k_convX(const float* __restrict__ src) {
    long i = (long)blockIdx.x * blockDim.x + threadIdx.x;
    if (i >= (long)NNODE * 64) return;
    int row = (int)(i >> 6);
    int c = (int)(i & 63) * 4;
    float4 v = *(const float4*)(src + (size_t)row * 256 + c);
    __half h0, h1, h2, h3, l0, l1, l2, l3;
    split1h(v.x, h0, l0); split1h(v.y, h1, l1); split1h(v.z, h2, l2); split1h(v.w, h3, l3);
    __half* p = g_Xs + (size_t)row * 512 + c;
    *(__half2*)(p)       = __halves2half2(h0, h1);
    *(__half2*)(p + 2)   = __halves2half2(h2, h3);
    *(__half2*)(p + 256) = __halves2half2(l0, l1);
    *(__half2*)(p + 258) = __halves2half2(l2, l3);
}

__global__ void k_convW(const float* __restrict__ Win, const float* __restrict__ Wh,
                        const float* __restrict__ Wg,  const float* __restrict__ Wl,
                        const float* __restrict__ Wp) {
    int idx = blockIdx.x * blockDim.x + threadIdx.x;
    if (idx >= WB_ROWS * 256) return;
    int row = idx >> 8;
    int k = idx & 255;
    float v = 0.f;
    if (row < 256) {
        v = Win[k * 256 + row];
    } else if (row < 2560) {
        int t = row - 256;
        int layer = t / 768;
        int r2 = t % 768;
        int mat = r2 >> 8;
        int n = r2 & 255;
        const float* W = (mat == 0 ? Wh : (mat == 1 ? Wg : Wl)) + (size_t)layer * 65536;
        v = W[k * 256 + n];
    } else {
        int n = row - 2560;
        if (n < 64) v = Wp[k * 64 + n];
    }
    g_WB[(size_t)row * 256 + k] = __float2half_rn(v);
}

// ---------------- HMMA fp16 2-term split GEMM + fused attention scores ------------
struct Seg {
    void* out;
    const float* bias1;
    const float* bias2;
    int relu;
    int ncols;   // valid cols (also row stride for fmt 0/2)
    int fmt;     // 0 = fp32 out, 1 = split fp16 out ([row,512] hi|lo), 2 = fp16 out
};

#define KC 64
#define A_BYTES (128 * KC * 2)     // 16KB
#define STAGE_BYTES (2 * A_BYTES)  // A + B = 32KB
#define SMEM_DYN (3 * STAGE_BYTES) // 96KB, 3-stage

__global__ void __launch_bounds__(256, 2)
k_gemm(const __half* __restrict__ A, const __half* __restrict__ Bm,
       int M, int tilesPerSeg, Seg s0, Seg s1, Seg s2,
       const float* __restrict__ attS, const float* __restrict__ attD, int attSeg,
       int nch0)
{
    extern __shared__ char smem[];
    uint32_t sb = smem_u32(smem);
    int tid = threadIdx.x;
    int lane = tid & 31, warp = tid >> 5;
    int wm = warp >> 1, wn = warp & 1;
    int mBase = blockIdx.y * 128;
    size_t bRow0 = (size_t)blockIdx.x * 128;
    int seg = blockIdx.x / tilesPerSeg;
    const int nch = (seg == 0) ? nch0 : NCH;

    float acc[2][8][4];
#pragma unroll
    for (int i = 0; i < 2; i++)
#pragma unroll
        for (int j = 0; j < 8; j++)
#pragma unroll
            for (int q = 0; q < 4; q++) acc[i][j][q] = 0.f;

    const uint32_t xm = (uint32_t)((lane & 7) << 4);
    const int rA = wm * 32 + ((lane >> 3) & 1) * 8 + (lane & 7);
    const int kAsel = lane >> 4;
    const int rBoff = ((lane >> 4) << 3) + (lane & 7);
    const int kBsel = (lane >> 3) & 1;

    auto load_chunk = [&](int c, int buf) {
        int ka = (c < 4) ? c * 64 : 256 + (c - 4) * 64;
        int kb = (c & 3) * 64;
        uint32_t aBuf = sb + buf * STAGE_BYTES;
        uint32_t bBuf = aBuf + A_BYTES;
#pragma unroll
        for (int it = 0; it < 4; it++) {
            int slot = tid + it * 256;
            int row = slot >> 3, kc = slot & 7;
            int gr = mBase + row;
            uint32_t off = (uint32_t)(row * 128 + kc * 16);
            uint32_t dst = aBuf + (off ^ ((uint32_t)(row & 7) << 4));
            const __half* src = A + (size_t)gr * 512 + ka + kc * 8;
            int sz = (gr < M) ? 16 : 0;
            CPA16(dst, src, sz);
        }
#pragma unroll
        for (int it = 0; it < 4; it++) {
            int slot = tid + it * 256;
            int row = slot >> 3, kc = slot & 7;
            uint32_t off = (uint32_t)(row * 128 + kc * 16);
            uint32_t dst = bBuf + (off ^ ((uint32_t)(row & 7) << 4));
            const __half* src = Bm + (bRow0 + row) * 256 + kb + kc * 8;
            CPA16(dst, src, 16);
        }
        CP_COMMIT();
    };

    load_chunk(0, 0);
    load_chunk(1, 1);

    for (int c = 0; c < nch; c++) {
        if (c + 2 < nch) { load_chunk(c + 2, (c + 2) % 3); CP_WAIT(2); }
        else if (c + 1 < nch) { CP_WAIT(1); }
        else { CP_WAIT(0); }
        __syncthreads();
        uint32_t aBuf = sb + (c % 3) * STAGE_BYTES;
        uint32_t bBuf = aBuf + A_BYTES;
#pragma unroll
        for (int kk = 0; kk < 4; kk++) {
            uint32_t a[2][4];
#pragma unroll
            for (int mt = 0; mt < 2; mt++) {
                uint32_t off = (uint32_t)((rA + mt * 16) * 128 + (kk * 2 + kAsel) * 16);
                uint32_t ad = aBuf + (off ^ xm);
                LDSM4(a[mt][0], a[mt][1], a[mt][2], a[mt][3], ad);
            }
            uint32_t b[4][4];
#pragma unroll
            for (int nt2 = 0; nt2 < 4; nt2++) {
                int rB = wn * 64 + nt2 * 16 + rBoff;
                uint32_t off = (uint32_t)(rB * 128 + (kk * 2 + kBsel) * 16);
                uint32_t ad = bBuf + (off ^ xm);
                LDSM4(b[nt2][0], b[nt2][1], b[nt2][2], b[nt2][3], ad);
            }
#pragma unroll
            for (int mt = 0; mt < 2; mt++)
#pragma unroll
                for (int nt = 0; nt < 8; nt++) {
                    uint32_t b0 = b[nt >> 1][(nt & 1) * 2];
                    uint32_t b1 = b[nt >> 1][(nt & 1) * 2 + 1];
                    MMA16816(acc[mt][nt], a[mt], b0, b1);
                }
        }
        __syncthreads();
    }

    int tileInSeg = blockIdx.x - seg * tilesPerSeg;
    Seg s = (seg == 0) ? s0 : (seg == 1) ? s1 : s2;
    int colSegBase = tileInSeg * 128 + wn * 64;
    int r0 = mBase + wm * 32 + (lane >> 2);
    const bool doAttn = (seg == attSeg);
    float aS[2][2], aD[2][2];   // [mt][row gr0 / gr1]
#pragma unroll
    for (int mt = 0; mt < 2; mt++) {
        aS[mt][0] = aS[mt][1] = 0.f;
        aD[mt][0] = aD[mt][1] = 0.f;
    }

#pragma unroll
    for (int mt = 0; mt < 2; mt++) {
        int gr0 = r0 + mt * 16;
        int gr1 = gr0 + 8;
#pragma unroll
        for (int nt = 0; nt < 8; nt++) {
            int col = colSegBase + nt * 8 + (lane & 3) * 2;
            if (col >= s.ncols) continue;
            float v0 = acc[mt][nt][0], v1 = acc[mt][nt][1];
            float v2 = acc[mt][nt][2], v3 = acc[mt][nt][3];
            if (doAttn) {
                float as0 = attS[col], as1 = attS[col + 1];
                float ad0 = attD[col], ad1 = attD[col + 1];
                aS[mt][0] += v0 * as0 + v1 * as1;
                aS[mt][1] += v2 * as0 + v3 * as1;
                aD[mt][0] += v0 * ad0 + v1 * ad1;
                aD[mt][1] += v2 * ad0 + v3 * ad1;
            }
            if (s.bias1) {
                float b0 = s.bias1[col], b1 = s.bias1[col + 1];
                v0 += b0; v1 += b1; v2 += b0; v3 += b1;
            }
            if (s.bias2) {
                float b0 = s.bias2[col], b1 = s.bias2[col + 1];
                v0 += b0; v1 += b1; v2 += b0; v3 += b1;
            }
            if (s.relu) {
                v0 = fmaxf(v0, 0.f); v1 = fmaxf(v1, 0.f);
                v2 = fmaxf(v2, 0.f); v3 = fmaxf(v3, 0.f);
            }
            if (s.fmt == 0) {
                if (gr0 < M) {
                    float2 p; p.x = v0; p.y = v1;
                    *(float2*)((float*)s.out + (size_t)gr0 * s.ncols + col) = p;
                }
                if (gr1 < M) {
                    float2 p; p.x = v2; p.y = v3;
                    *(float2*)((float*)s.out + (size_t)gr1 * s.ncols + col) = p;
                }
            } else if (s.fmt == 2) {
                if (gr0 < M)
                    *(__half2*)((__half*)s.out + (size_t)gr0 * s.ncols + col) = __floats2half2_rn(v0, v1);
                if (gr1 < M)
                    *(__half2*)((__half*)s.out + (size_t)gr1 * s.ncols + col) = __floats2half2_rn(v2, v3);
            } else {
                if (gr0 < M) {
                    __half* op = (__half*)s.out + (size_t)gr0 * 512;
                    __half h0, l0, h1, l1;
                    split1h(v0, h0, l0); split1h(v1, h1, l1);
                    *(__half2*)(op + col) = __halves2half2(h0, h1);
                    *(__half2*)(op + 256 + col) = __halves2half2(l0, l1);
                }
                if (gr1 < M) {
                    __half* op = (__half*)s.out + (size_t)gr1 * 512;
                    __half h0, l0, h1, l1;
                    split1h(v2, h0, l0); split1h(v3, h1, l1);
                    *(__half2*)(op + col) = __halves2half2(h0, h1);
                    *(__half2*)(op + 256 + col) = __halves2half2(l0, l1);
                }
            }
        }
    }

    if (doAttn) {
        int head = colSegBase >> 6;   // tileInSeg*2 + wn, constant per warp
#pragma unroll
        for (int mt = 0; mt < 2; mt++) {
            float s0 = aS[mt][0], s1v = aS[mt][1];
            float d0 = aD[mt][0], d1 = aD[mt][1];
            s0  += __shfl_xor_sync(0xffffffffu, s0, 1);
            s0  += __shfl_xor_sync(0xffffffffu, s0, 2);
            s1v += __shfl_xor_sync(0xffffffffu, s1v, 1);
            s1v += __shfl_xor_sync(0xffffffffu, s1v, 2);
            d0  += __shfl_xor_sync(0xffffffffu, d0, 1);
            d0  += __shfl_xor_sync(0xffffffffu, d0, 2);
            d1  += __shfl_xor_sync(0xffffffffu, d1, 1);
            d1  += __shfl_xor_sync(0xffffffffu, d1, 2);
            if ((lane & 3) == 0) {
                int gr0 = r0 + mt * 16, gr1 = gr0 + 8;
                if (gr0 < M) { g_ASRC[gr0 * 4 + head] = s0;  g_ADST[gr0 * 4 + head] = d0; }
                if (gr1 < M) { g_ASRC[gr1 * 4 + head] = s1v; g_ADST[gr1 * 4 + head] = d1; }
            }
        }
    }
}

// ---------------- fused GAT + residual + relu + LN + gate (4-edge unrolled) -------
__global__ void __launch_bounds__(256)
k_gat(const float* __restrict__ lng, const float* __restrict__ lnb,
      const float* __restrict__ betas, int accumulate, int writeX2, int writeXs)
{
    int warp = blockIdx.x * (blockDim.x >> 5) + (threadIdx.x >> 5);
    int lane = threadIdx.x & 31;
    if (warp >= NNODE) return;
    int n = warp;
    int h = lane >> 3;
    int c = lane * 8;
    int start = g_rowptr[n], end = g_rowptr[n + 1];
    float adst_h = g_ADST[n * 4 + h];

    float acc[8];
#pragma unroll
    for (int k = 0; k < 8; k++) acc[k] = 0.f;
    float den = 0.f;

    int j = start;
    // 4-edge unrolled main loop: batch all loads first for MLP
    for (; j + 3 < end; j += 4) {
        int s0i = g_colsrc[j],     s1i = g_colsrc[j + 1];
        int s2i = g_colsrc[j + 2], s3i = g_colsrc[j + 3];
        float as0 = __ldg(&g_ASRC[s0i * 4 + h]);
        float as1 = __ldg(&g_ASRC[s1i * 4 + h]);
        float as2 = __ldg(&g_ASRC[s2i * 4 + h]);
        float as3 = __ldg(&g_ASRC[s3i * 4 + h]);
        uint4 v0 = *(const uint4*)(g_HG + (size_t)s0i * 256 + c);
        uint4 v1 = *(const uint4*)(g_HG + (size_t)s1i * 256 + c);
        uint4 v2 = *(const uint4*)(g_HG + (size_t)s2i * 256 + c);
        uint4 v3 = *(const uint4*)(g_HG + (size_t)s3i * 256 + c);
        float w0 = __expf(lrelu(as0 + adst_h));
        float w1 = __expf(lrelu(as1 + adst_h));
        float w2 = __expf(lrelu(as2 + adst_h));
        float w3 = __expf(lrelu(as3 + adst_h));
        den += (w0 + w1) + (w2 + w3);
        const __half2* h0p = (const __half2*)&v0;
        const __half2* h1p = (const __half2*)&v1;
        const __half2* h2p = (const __half2*)&v2;
        const __half2* h3p = (const __half2*)&v3;
#pragma unroll
        for (int k = 0; k < 4; k++) {
            float2 f0 = __half22float2(h0p[k]);
            float2 f1 = __half22float2(h1p[k]);
            float2 f2 = __half22float2(h2p[k]);
            float2 f3 = __half22float2(h3p[k]);
            acc[2 * k]     += (w0 * f0.x + w1 * f1.x) + (w2 * f2.x + w3 * f3.x);
            acc[2 * k + 1] += (w0 * f0.y + w1 * f1.y) + (w2 * f2.y + w3 * f3.y);
        }
    }
    for (; j < end; j++) {
        int s = g_colsrc[j];
        float as = __ldg(&g_ASRC[s * 4 + h]);
        uint4 v = *(const uint4*)(g_HG + (size_t)s * 256 + c);
        float w = __expf(lrelu(as + adst_h));
        den += w;
        const __half2* hh = (const __half2*)&v;
#pragma unroll
        for (int k = 0; k < 4; k++) {
            float2 f = __half22float2(hh[k]);
            acc[2 * k]     += w * f.x;
            acc[2 * k + 1] += w * f.y;
        }
    }
    float inv = 1.f / den;

    uint4 gv = *(const uint4*)(g_GXL + (size_t)n * DMODEL + c);
    uint4 hv = *(const uint4*)(g_H   + (size_t)n * DMODEL + c);
    float gArr[8], hArr[8];
    half8_to_float(gv, gArr);
    half8_to_float(hv, hArr);
    float xv[8], tv[8];
    float s1 = 0.f, s2 = 0.f;
#pragma unroll
    for (int k = 0; k < 8; k++) {
        xv[k] = fmaxf(acc[k] * inv + gArr[k], 0.f);
        tv[k] = hArr[k] * xv[k];
        s1 += tv[k];
        s2 += tv[k] * tv[k];
    }
#pragma unroll
    for (int off = 16; off >= 1; off >>= 1) {
        s1 += __shfl_xor_sync(0xffffffffu, s1, off);
        s2 += __shfl_xor_sync(0xffffffffu, s2, off);
    }
    float mu  = s1 * (1.f / 256.f);
    float var = s2 * (1.f / 256.f) - mu * mu;
    float rstd = rsqrtf(var + LN_EPS);

    const float4* lg = (const float4*)(lng + c);
    const float4* lb = (const float4*)(lnb + c);
    const float4* bt = (const float4*)(betas + c);
    float4 lg0 = lg[0], lg1 = lg[1];
    float4 lb0 = lb[0], lb1 = lb[1];
    float4 bt0 = bt[0], bt1 = bt[1];
    float lgA[8] = {lg0.x, lg0.y, lg0.z, lg0.w, lg1.x, lg1.y, lg1.z, lg1.w};
    float lbA[8] = {lb0.x, lb0.y, lb0.z, lb0.w, lb1.x, lb1.y, lb1.z, lb1.w};
    float btA[8] = {bt0.x, bt0.y, bt0.z, bt0.w, bt1.x, bt1.y, bt1.z, bt1.w};

    float o[8];
#pragma unroll
    for (int k = 0; k < 8; k++) {
        float b = sigm(btA[k]);
        o[k] = (1.f - b) * ((tv[k] - mu) * rstd * lgA[k] + lbA[k]) + b * xv[k];
    }

    if (writeX2) store_split8h(g_X2 + (size_t)n * 512, c, o);

    float* XL = g_XLOC + (size_t)n * DMODEL + c;
    float xl[8];
    if (accumulate) {
        float4 a0 = *(const float4*)(XL);
        float4 a1 = *(const float4*)(XL + 4);
        float aArr[8] = {a0.x, a0.y, a0.z, a0.w, a1.x, a1.y, a1.z, a1.w};
#pragma unroll
        for (int k = 0; k < 8; k++) xl[k] = aArr[k] + o[k];
    } else {
#pragma unroll
        for (int k = 0; k < 8; k++) xl[k] = o[k];
    }
    *(float4*)(XL)     = make_float4(xl[0], xl[1], xl[2], xl[3]);
    *(float4*)(XL + 4) = make_float4(xl[4], xl[5], xl[6], xl[7]);

    if (writeXs) store_split8h(g_Xs + (size_t)n * 512, c, xl);
}

// ---------------- host ------------------------------------------------------------
extern "C" void kernel_launch(void* const* d_in, const int* in_sizes, int n_in,
                              void* d_out, int out_size)
{
    const float* x       = (const float*)d_in[0];
    const int*   ei      = (const int*)  d_in[1];
    const float* Win     = (const float*)d_in[2];
    const float* b_in    = (const float*)d_in[3];
    const float* Wh      = (const float*)d_in[4];
    const float* bh      = (const float*)d_in[5];
    const float* Wg      = (const float*)d_in[6];
    const float* att_src = (const float*)d_in[7];
    const float* att_dst = (const float*)d_in[8];
    const float* bg      = (const float*)d_in[9];
    const float* Wl      = (const float*)d_in[10];
    const float* bl      = (const float*)d_in[11];
    const float* ln_g    = (const float*)d_in[12];
    const float* ln_b    = (const float*)d_in[13];
    const float* betas   = (const float*)d_in[14];
    const float* Wp      = (const float*)d_in[15];
    const float* bp      = (const float*)d_in[16];
    float* out = (float*)d_out;

    cudaFuncSetAttribute(k_gemm, cudaFuncAttributeMaxDynamicSharedMemorySize, SMEM_DYN);

    __half *pXs, *pX2, *pWB, *pHG, *pH, *pGXL;
    cudaGetSymbolAddress((void**)&pXs,  g_Xs);
    cudaGetSymbolAddress((void**)&pX2,  g_X2);
    cudaGetSymbolAddress((void**)&pWB,  g_WB);
    cudaGetSymbolAddress((void**)&pH,   g_H);
    cudaGetSymbolAddress((void**)&pHG,  g_HG);
    cudaGetSymbolAddress((void**)&pGXL, g_GXL);

    const int MT = (NNODE + 127) / 128;   // 782
    Seg z = {nullptr, nullptr, nullptr, 0, 256, 0};

    // launches 1-3, then launch 4 = X0 GEMM (ncu captures the 4th launch)
    k_convX<<<(NNODE * 64 + 255) / 256, 256>>>(x);                       // 1
    k_convW<<<(WB_ROWS * 256 + 255) / 256, 256>>>(Win, Wh, Wg, Wl, Wp); // 2
    k_zero_deg<<<(NNODE + 255) / 256, 256>>>();                          // 3
    {
        Seg s0 = {pX2, b_in, nullptr, 0, 256, 1};
        k_gemm<<<dim3(2, MT), 256, SMEM_DYN>>>(pXs, pWB, NNODE, 2, s0, z, z,
                                               nullptr, nullptr, -1, NCH);  // 4 (profiled)
    }

    // CSR build
    k_count<<<(NE_TOT + 255) / 256, 256>>>(ei);
    const int NSB = (NNODE + 1023) / 1024;
    k_scan1<<<NSB, 1024>>>();
    k_scan2<<<1, 128>>>(NSB);
    k_scan3<<<(NNODE + 255) / 256, 256>>>();
    k_fill<<<(NE_TOT + 255) / 256, 256>>>(ei);

    int warpBlocks = (NNODE + 7) / 8;
    for (int i = 0; i < NLAYER; i++) {
        Seg sH  = {pH,   bh + i * DMODEL, nullptr,         1, 256, 2};
        Seg sHG = {pHG,  nullptr,          nullptr,         0, 256, 2};
        Seg sGX = {pGXL, bl + i * DMODEL, bg + i * DMODEL,  0, 256, 2};
        // attention scores fused into the HG (seg 1) epilogue;
        // H segment (seg 0) runs A-hi only (nch0 = 4): H feeds only h*x -> LN.
        k_gemm<<<dim3(6, MT), 256, SMEM_DYN>>>(pX2, pWB + (size_t)(256 + i * 768) * 256,
                                               NNODE, 2, sH, sHG, sGX,
                                               att_src + i * NHEAD * 64,
                                               att_dst + i * NHEAD * 64, 1, 4);
        int last = (i == NLAYER - 1);
        k_gat<<<warpBlocks, 256>>>(ln_g + i * DMODEL, ln_b + i * DMODEL, betas + i * DMODEL,
                                   i, !last, last);
    }

    // out = XLOC @ Wp + bp, A-hi only (direct output; dropped-term error ~1.4e-4
    // adds in quadrature to existing 8.2e-4 -> negligible shift, half the work)
    {
        Seg s0 = {out, bp, nullptr, 0, 64, 0};
        k_gemm<<<dim3(1, MT), 256, SMEM_DYN>>>(pXs, pWB + (size_t)2560 * 256, NNODE, 1, s0, z, z,
                                               nullptr, nullptr, -1, 4);
    }
}

// round 16
// speedup vs baseline: 1.1330x; 1.0563x over previous
#include <cuda_runtime.h>
#include <cuda_bf16.h>
#include <cuda_fp16.h>
#include <math.h>
#include <stdint.h>

#define NNODE 100000
#define NEDGE 1600000
#define NE_TOT (NEDGE + NNODE)
#define DMODEL 256
#define NHEAD 4
#define NLAYER 3
#define NOUTC 64
#define LRELU_SLOPE 0.2f
#define LN_EPS 1e-5f

#define NCH 8               // 8 K-chunks of 64 (K' = 512: Ahi·B + Alo·B)
#define WB_ROWS 2816        // 256 (Win) + 3*768 (Wh|Wg|Wl) + 256 (Wp padded)

// ---------------- scratch ---------------------------------------------------------
__device__ __half g_Xs[(size_t)NNODE * 512];   // staging split fp16 (x input / XLOC)
__device__ __half g_X2[(size_t)NNODE * 512];   // live split fp16 X between layers
__device__ __half g_WB[(size_t)WB_ROWS * 256]; // fp16 transposed weights (hi only)
__device__ __half g_H[(size_t)NNODE * DMODEL];  // fp16 (elementwise use only)
__device__ __half g_HG[(size_t)NNODE * DMODEL]; // fp16: 50MB, L2-resident
__device__ __half g_GXL[(size_t)NNODE * DMODEL];// fp16 (elementwise use only)
__device__ float  g_XLOC[(size_t)NNODE * DMODEL];
__device__ float  g_ASRC[NNODE * NHEAD];
__device__ float  g_ADST[NNODE * NHEAD];
__device__ int    g_deg[NNODE];
__device__ int    g_rowptr[NNODE + 1];
__device__ int    g_cursor[NNODE];
__device__ int    g_colsrc[NE_TOT];
__device__ int    g_bsum[128];
__device__ int    g_boff[128];

// ---------------- asm helpers (sm_80-era features: valid on sm_103 base) ----------
__device__ __forceinline__ uint32_t smem_u32(const void* p) {
    uint32_t a;
    asm("{ .reg .u64 t; cvta.to.shared.u64 t, %1; cvt.u32.u64 %0, t; }" : "=r"(a) : "l"(p));
    return a;
}
#define LDSM4(r0,r1,r2,r3, addr) \
    asm volatile("ldmatrix.sync.aligned.m8n8.x4.shared.b16 {%0,%1,%2,%3}, [%4];" \
        : "=r"(r0),"=r"(r1),"=r"(r2),"=r"(r3) : "r"(addr))
#define MMA16816(d, a, b0, b1) \
    asm volatile("mma.sync.aligned.m16n8k16.row.col.f32.f16.f16.f32 " \
        "{%0,%1,%2,%3},{%4,%5,%6,%7},{%8,%9},{%0,%1,%2,%3};" \
        : "+f"((d)[0]),"+f"((d)[1]),"+f"((d)[2]),"+f"((d)[3]) \
        : "r"((a)[0]),"r"((a)[1]),"r"((a)[2]),"r"((a)[3]),"r"(b0),"r"(b1))
#define CPA16(dst, src, sz) \
    asm volatile("cp.async.cg.shared.global [%0], [%1], 16, %2;" :: "r"(dst),"l"(src),"r"(sz))
#define CP_COMMIT() asm volatile("cp.async.commit_group;" ::: "memory")
#define CP_WAIT(n)  asm volatile("cp.async.wait_group %0;" :: "n"(n) : "memory")

__device__ __forceinline__ void split1h(float v, __half& h, __half& l) {
    h = __float2half_rn(v);
    l = __float2half_rn(v - __half2float(h));
}
__device__ __forceinline__ float lrelu(float e) { return e > 0.f ? e : LRELU_SLOPE * e; }
__device__ __forceinline__ float sigm(float x)  { return 1.f / (1.f + __expf(-x)); }

// write 8 floats as split fp16 (hi at [c..c+8), lo at [256+c..)) in a 512-wide row
__device__ __forceinline__ void store_split8h(__half* rowp, int c, const float* v) {
    __half2 hp[4], lp[4];
#pragma unroll
    for (int k = 0; k < 4; k++) {
        __half h0, l0, h1, l1;
        split1h(v[2 * k],     h0, l0);
        split1h(v[2 * k + 1], h1, l1);
        hp[k] = __halves2half2(h0, h1);
        lp[k] = __halves2half2(l0, l1);
    }
    *(uint4*)(rowp + c)       = *(uint4*)hp;
    *(uint4*)(rowp + 256 + c) = *(uint4*)lp;
}

// unpack 8 fp16 (as uint4) into floats
__device__ __forceinline__ void half8_to_float(const uint4& v, float* f) {
    const __half2* hh = (const __half2*)&v;
#pragma unroll
    for (int k = 0; k < 4; k++) {
        float2 p = __half22float2(hh[k]);
        f[2 * k] = p.x; f[2 * k + 1] = p.y;
    }
}

// ---------------- CSR build -------------------------------------------------------
__global__ void k_zero_deg() {
    int i = blockIdx.x * blockDim.x + threadIdx.x;
    if (i < NNODE) g_deg[i] = 0;
}
__global__ void k_count(const int* __restrict__ ei) {
    int e = blockIdx.x * blockDim.x + threadIdx.x;
    if (e >= NE_TOT) return;
    int d = (e < NEDGE) ? ei[NEDGE + e] : (e - NEDGE);
    atomicAdd(&g_deg[d], 1);
}
__global__ void k_scan1() {
    __shared__ int sh[1024];
    int b = blockIdx.x, t = threadIdx.x;
    int i = b * 1024 + t;
    int v = (i < NNODE) ? g_deg[i] : 0;
    sh[t] = v;
    __syncthreads();
#pragma unroll
    for (int off = 1; off < 1024; off <<= 1) {
        int u = (t >= off) ? sh[t - off] : 0;
        __syncthreads();
        sh[t] += u;
        __syncthreads();
    }
    if (i < NNODE) g_rowptr[i] = sh[t] - v;
    if (t == 1023) g_bsum[b] = sh[1023];
}
__global__ void k_scan2(int nsb) {
    __shared__ int sh[128];
    int t = threadIdx.x;
    int v = (t < nsb) ? g_bsum[t] : 0;
    sh[t] = v;
    __syncthreads();
#pragma unroll
    for (int off = 1; off < 128; off <<= 1) {
        int u = (t >= off) ? sh[t - off] : 0;
        __syncthreads();
        sh[t] += u;
        __syncthreads();
    }
    g_boff[t] = sh[t] - v;
}
__global__ void k_scan3() {
    int i = blockIdx.x * blockDim.x + threadIdx.x;
    if (i >= NNODE) return;
    int r = g_rowptr[i] + g_boff[i >> 10];
    g_rowptr[i] = r;
    g_cursor[i] = r;
    if (i == 0) g_rowptr[NNODE] = NE_TOT;
}
__global__ void k_fill(const int* __restrict__ ei) {
    int e = blockIdx.x * blockDim.x + threadIdx.x;
    if (e >= NE_TOT) return;
    int s, d;
    if (e < NEDGE) { s = ei[e]; d = ei[NEDGE + e]; }
    else           { s = e - NEDGE; d = s; }
    int pos = atomicAdd(&g_cursor[d], 1);
    g_colsrc[pos] = s;
}

// ---------------- conversions -----------------------------------------------------
__global__ void k_convX(const float* __restrict__ src) {
    long i = (long)blockIdx.x * blockDim.x + threadIdx.x;
    if (i >= (long)NNODE * 64) return;
    int row = (int)(i >> 6);
    int c = (int)(i & 63) * 4;
    float4 v = *(const float4*)(src + (size_t)row * 256 + c);
    __half h0, h1, h2, h3, l0, l1, l2, l3;
    split1h(v.x, h0, l0); split1h(v.y, h1, l1); split1h(v.z, h2, l2); split1h(v.w, h3, l3);
    __half* p = g_Xs + (size_t)row * 512 + c;
    *(__half2*)(p)       = __halves2half2(h0, h1);
    *(__half2*)(p + 2)   = __halves2half2(h2, h3);
    *(__half2*)(p + 256) = __halves2half2(l0, l1);
    *(__half2*)(p + 258) = __halves2half2(l2, l3);
}

__global__ void k_convW(const float* __restrict__ Win, const float* __restrict__ Wh,
                        const float* __restrict__ Wg,  const float* __restrict__ Wl,
                        const float* __restrict__ Wp) {
    int idx = blockIdx.x * blockDim.x + threadIdx.x;
    if (idx >= WB_ROWS * 256) return;
    int row = idx >> 8;
    int k = idx & 255;
    float v = 0.f;
    if (row < 256) {
        v = Win[k * 256 + row];
    } else if (row < 2560) {
        int t = row - 256;
        int layer = t / 768;
        int r2 = t % 768;
        int mat = r2 >> 8;
        int n = r2 & 255;
        const float* W = (mat == 0 ? Wh : (mat == 1 ? Wg : Wl)) + (size_t)layer * 65536;
        v = W[k * 256 + n];
    } else {
        int n = row - 2560;
        if (n < 64) v = Wp[k * 64 + n];
    }
    g_WB[(size_t)row * 256 + k] = __float2half_rn(v);
}

// ---------------- HMMA fp16 2-term split GEMM + fused attention scores ------------
// Segments whose bit is set in hiMask run A-hi only (4 chunks instead of 8).
struct Seg {
    void* out;
    const float* bias1;
    const float* bias2;
    int relu;
    int ncols;   // valid cols (also row stride for fmt 0/2)
    int fmt;     // 0 = fp32 out, 1 = split fp16 out ([row,512] hi|lo), 2 = fp16 out
};

#define KC 64
#define A_BYTES (128 * KC * 2)     // 16KB
#define STAGE_BYTES (2 * A_BYTES)  // A + B = 32KB
#define SMEM_DYN (3 * STAGE_BYTES) // 96KB, 3-stage

__global__ void __launch_bounds__(256, 2)
k_gemm(const __half* __restrict__ A, const __half* __restrict__ Bm,
       int M, int tilesPerSeg, Seg s0, Seg s1, Seg s2,
       const float* __restrict__ attS, const float* __restrict__ attD, int attSeg,
       int hiMask)
{
    extern __shared__ char smem[];
    uint32_t sb = smem_u32(smem);
    int tid = threadIdx.x;
    int lane = tid & 31, warp = tid >> 5;
    int wm = warp >> 1, wn = warp & 1;
    int mBase = blockIdx.y * 128;
    size_t bRow0 = (size_t)blockIdx.x * 128;
    int seg = blockIdx.x / tilesPerSeg;
    const int nch = ((hiMask >> seg) & 1) ? 4 : NCH;

    float acc[2][8][4];
#pragma unroll
    for (int i = 0; i < 2; i++)
#pragma unroll
        for (int j = 0; j < 8; j++)
#pragma unroll
            for (int q = 0; q < 4; q++) acc[i][j][q] = 0.f;

    const uint32_t xm = (uint32_t)((lane & 7) << 4);
    const int rA = wm * 32 + ((lane >> 3) & 1) * 8 + (lane & 7);
    const int kAsel = lane >> 4;
    const int rBoff = ((lane >> 4) << 3) + (lane & 7);
    const int kBsel = (lane >> 3) & 1;

    auto load_chunk = [&](int c, int buf) {
        int ka = (c < 4) ? c * 64 : 256 + (c - 4) * 64;
        int kb = (c & 3) * 64;
        uint32_t aBuf = sb + buf * STAGE_BYTES;
        uint32_t bBuf = aBuf + A_BYTES;
#pragma unroll
        for (int it = 0; it < 4; it++) {
            int slot = tid + it * 256;
            int row = slot >> 3, kc = slot & 7;
            int gr = mBase + row;
            uint32_t off = (uint32_t)(row * 128 + kc * 16);
            uint32_t dst = aBuf + (off ^ ((uint32_t)(row & 7) << 4));
            const __half* src = A + (size_t)gr * 512 + ka + kc * 8;
            int sz = (gr < M) ? 16 : 0;
            CPA16(dst, src, sz);
        }
#pragma unroll
        for (int it = 0; it < 4; it++) {
            int slot = tid + it * 256;
            int row = slot >> 3, kc = slot & 7;
            uint32_t off = (uint32_t)(row * 128 + kc * 16);
            uint32_t dst = bBuf + (off ^ ((uint32_t)(row & 7) << 4));
            const __half* src = Bm + (bRow0 + row) * 256 + kb + kc * 8;
            CPA16(dst, src, 16);
        }
        CP_COMMIT();
    };

    load_chunk(0, 0);
    load_chunk(1, 1);

    for (int c = 0; c < nch; c++) {
        if (c + 2 < nch) { load_chunk(c + 2, (c + 2) % 3); CP_WAIT(2); }
        else if (c + 1 < nch) { CP_WAIT(1); }
        else { CP_WAIT(0); }
        __syncthreads();
        uint32_t aBuf = sb + (c % 3) * STAGE_BYTES;
        uint32_t bBuf = aBuf + A_BYTES;
#pragma unroll
        for (int kk = 0; kk < 4; kk++) {
            uint32_t a[2][4];
#pragma unroll
            for (int mt = 0; mt < 2; mt++) {
                uint32_t off = (uint32_t)((rA + mt * 16) * 128 + (kk * 2 + kAsel) * 16);
                uint32_t ad = aBuf + (off ^ xm);
                LDSM4(a[mt][0], a[mt][1], a[mt][2], a[mt][3], ad);
            }
            uint32_t b[4][4];
#pragma unroll
            for (int nt2 = 0; nt2 < 4; nt2++) {
                int rB = wn * 64 + nt2 * 16 + rBoff;
                uint32_t off = (uint32_t)(rB * 128 + (kk * 2 + kBsel) * 16);
                uint32_t ad = bBuf + (off ^ xm);
                LDSM4(b[nt2][0], b[nt2][1], b[nt2][2], b[nt2][3], ad);
            }
#pragma unroll
            for (int mt = 0; mt < 2; mt++)
#pragma unroll
                for (int nt = 0; nt < 8; nt++) {
                    uint32_t b0 = b[nt >> 1][(nt & 1) * 2];
                    uint32_t b1 = b[nt >> 1][(nt & 1) * 2 + 1];
                    MMA16816(acc[mt][nt], a[mt], b0, b1);
                }
        }
        __syncthreads();
    }

    int tileInSeg = blockIdx.x - seg * tilesPerSeg;
    Seg s = (seg == 0) ? s0 : (seg == 1) ? s1 : s2;
    int colSegBase = tileInSeg * 128 + wn * 64;
    int r0 = mBase + wm * 32 + (lane >> 2);
    const bool doAttn = (seg == attSeg);
    float aS[2][2], aD[2][2];   // [mt][row gr0 / gr1]
#pragma unroll
    for (int mt = 0; mt < 2; mt++) {
        aS[mt][0] = aS[mt][1] = 0.f;
        aD[mt][0] = aD[mt][1] = 0.f;
    }

#pragma unroll
    for (int mt = 0; mt < 2; mt++) {
        int gr0 = r0 + mt * 16;
        int gr1 = gr0 + 8;
#pragma unroll
        for (int nt = 0; nt < 8; nt++) {
            int col = colSegBase + nt * 8 + (lane & 3) * 2;
            if (col >= s.ncols) continue;
            float v0 = acc[mt][nt][0], v1 = acc[mt][nt][1];
            float v2 = acc[mt][nt][2], v3 = acc[mt][nt][3];
            if (doAttn) {
                float as0 = attS[col], as1 = attS[col + 1];
                float ad0 = attD[col], ad1 = attD[col + 1];
                aS[mt][0] += v0 * as0 + v1 * as1;
                aS[mt][1] += v2 * as0 + v3 * as1;
                aD[mt][0] += v0 * ad0 + v1 * ad1;
                aD[mt][1] += v2 * ad0 + v3 * ad1;
            }
            if (s.bias1) {
                float b0 = s.bias1[col], b1 = s.bias1[col + 1];
                v0 += b0; v1 += b1; v2 += b0; v3 += b1;
            }
            if (s.bias2) {
                float b0 = s.bias2[col], b1 = s.bias2[col + 1];
                v0 += b0; v1 += b1; v2 += b0; v3 += b1;
            }
            if (s.relu) {
                v0 = fmaxf(v0, 0.f); v1 = fmaxf(v1, 0.f);
                v2 = fmaxf(v2, 0.f); v3 = fmaxf(v3, 0.f);
            }
            if (s.fmt == 0) {
                if (gr0 < M) {
                    float2 p; p.x = v0; p.y = v1;
                    *(float2*)((float*)s.out + (size_t)gr0 * s.ncols + col) = p;
                }
                if (gr1 < M) {
                    float2 p; p.x = v2; p.y = v3;
                    *(float2*)((float*)s.out + (size_t)gr1 * s.ncols + col) = p;
                }
            } else if (s.fmt == 2) {
                if (gr0 < M)
                    *(__half2*)((__half*)s.out + (size_t)gr0 * s.ncols + col) = __floats2half2_rn(v0, v1);
                if (gr1 < M)
                    *(__half2*)((__half*)s.out + (size_t)gr1 * s.ncols + col) = __floats2half2_rn(v2, v3);
            } else {
                if (gr0 < M) {
                    __half* op = (__half*)s.out + (size_t)gr0 * 512;
                    __half h0, l0, h1, l1;
                    split1h(v0, h0, l0); split1h(v1, h1, l1);
                    *(__half2*)(op + col) = __halves2half2(h0, h1);
                    *(__half2*)(op + 256 + col) = __halves2half2(l0, l1);
                }
                if (gr1 < M) {
                    __half* op = (__half*)s.out + (size_t)gr1 * 512;
                    __half h0, l0, h1, l1;
                    split1h(v2, h0, l0); split1h(v3, h1, l1);
                    *(__half2*)(op + col) = __halves2half2(h0, h1);
                    *(__half2*)(op + 256 + col) = __halves2half2(l0, l1);
                }
            }
        }
    }

    if (doAttn) {
        int head = colSegBase >> 6;   // tileInSeg*2 + wn, constant per warp
#pragma unroll
        for (int mt = 0; mt < 2; mt++) {
            float s0 = aS[mt][0], s1v = aS[mt][1];
            float d0 = aD[mt][0], d1 = aD[mt][1];
            s0  += __shfl_xor_sync(0xffffffffu, s0, 1);
            s0  += __shfl_xor_sync(0xffffffffu, s0, 2);
            s1v += __shfl_xor_sync(0xffffffffu, s1v, 1);
            s1v += __shfl_xor_sync(0xffffffffu, s1v, 2);
            d0  += __shfl_xor_sync(0xffffffffu, d0, 1);
            d0  += __shfl_xor_sync(0xffffffffu, d0, 2);
            d1  += __shfl_xor_sync(0xffffffffu, d1, 1);
            d1  += __shfl_xor_sync(0xffffffffu, d1, 2);
            if ((lane & 3) == 0) {
                int gr0 = r0 + mt * 16, gr1 = gr0 + 8;
                if (gr0 < M) { g_ASRC[gr0 * 4 + head] = s0;  g_ADST[gr0 * 4 + head] = d0; }
                if (gr1 < M) { g_ASRC[gr1 * 4 + head] = s1v; g_ADST[gr1 * 4 + head] = d1; }
            }
        }
    }
}

// ---------------- fused GAT + residual + relu + LN + gate (4-edge unrolled) -------
__global__ void __launch_bounds__(256)
k_gat(const float* __restrict__ lng, const float* __restrict__ lnb,
      const float* __restrict__ betas, int accumulate, int writeX2, int writeXs)
{
    int warp = blockIdx.x * (blockDim.x >> 5) + (threadIdx.x >> 5);
    int lane = threadIdx.x & 31;
    if (warp >= NNODE) return;
    int n = warp;
    int h = lane >> 3;
    int c = lane * 8;
    int start = g_rowptr[n], end = g_rowptr[n + 1];
    float adst_h = g_ADST[n * 4 + h];

    float acc[8];
#pragma unroll
    for (int k = 0; k < 8; k++) acc[k] = 0.f;
    float den = 0.f;

    int j = start;
    for (; j + 3 < end; j += 4) {
        int s0i = g_colsrc[j],     s1i = g_colsrc[j + 1];
        int s2i = g_colsrc[j + 2], s3i = g_colsrc[j + 3];
        float as0 = __ldg(&g_ASRC[s0i * 4 + h]);
        float as1 = __ldg(&g_ASRC[s1i * 4 + h]);
        float as2 = __ldg(&g_ASRC[s2i * 4 + h]);
        float as3 = __ldg(&g_ASRC[s3i * 4 + h]);
        uint4 v0 = *(const uint4*)(g_HG + (size_t)s0i * 256 + c);
        uint4 v1 = *(const uint4*)(g_HG + (size_t)s1i * 256 + c);
        uint4 v2 = *(const uint4*)(g_HG + (size_t)s2i * 256 + c);
        uint4 v3 = *(const uint4*)(g_HG + (size_t)s3i * 256 + c);
        float w0 = __expf(lrelu(as0 + adst_h));
        float w1 = __expf(lrelu(as1 + adst_h));
        float w2 = __expf(lrelu(as2 + adst_h));
        float w3 = __expf(lrelu(as3 + adst_h));
        den += (w0 + w1) + (w2 + w3);
        const __half2* h0p = (const __half2*)&v0;
        const __half2* h1p = (const __half2*)&v1;
        const __half2* h2p = (const __half2*)&v2;
        const __half2* h3p = (const __half2*)&v3;
#pragma unroll
        for (int k = 0; k < 4; k++) {
            float2 f0 = __half22float2(h0p[k]);
            float2 f1 = __half22float2(h1p[k]);
            float2 f2 = __half22float2(h2p[k]);
            float2 f3 = __half22float2(h3p[k]);
            acc[2 * k]     += (w0 * f0.x + w1 * f1.x) + (w2 * f2.x + w3 * f3.x);
            acc[2 * k + 1] += (w0 * f0.y + w1 * f1.y) + (w2 * f2.y + w3 * f3.y);
        }
    }
    for (; j < end; j++) {
        int s = g_colsrc[j];
        float as = __ldg(&g_ASRC[s * 4 + h]);
        uint4 v = *(const uint4*)(g_HG + (size_t)s * 256 + c);
        float w = __expf(lrelu(as + adst_h));
        den += w;
        const __half2* hh = (const __half2*)&v;
#pragma unroll
        for (int k = 0; k < 4; k++) {
            float2 f = __half22float2(hh[k]);
            acc[2 * k]     += w * f.x;
            acc[2 * k + 1] += w * f.y;
        }
    }
    float inv = 1.f / den;

    uint4 gv = *(const uint4*)(g_GXL + (size_t)n * DMODEL + c);
    uint4 hv = *(const uint4*)(g_H   + (size_t)n * DMODEL + c);
    float gArr[8], hArr[8];
    half8_to_float(gv, gArr);
    half8_to_float(hv, hArr);
    float xv[8], tv[8];
    float s1 = 0.f, s2 = 0.f;
#pragma unroll
    for (int k = 0; k < 8; k++) {
        xv[k] = fmaxf(acc[k] * inv + gArr[k], 0.f);
        tv[k] = hArr[k] * xv[k];
        s1 += tv[k];
        s2 += tv[k] * tv[k];
    }
#pragma unroll
    for (int off = 16; off >= 1; off >>= 1) {
        s1 += __shfl_xor_sync(0xffffffffu, s1, off);
        s2 += __shfl_xor_sync(0xffffffffu, s2, off);
    }
    float mu  = s1 * (1.f / 256.f);
    float var = s2 * (1.f / 256.f) - mu * mu;
    float rstd = rsqrtf(var + LN_EPS);

    const float4* lg = (const float4*)(lng + c);
    const float4* lb = (const float4*)(lnb + c);
    const float4* bt = (const float4*)(betas + c);
    float4 lg0 = lg[0], lg1 = lg[1];
    float4 lb0 = lb[0], lb1 = lb[1];
    float4 bt0 = bt[0], bt1 = bt[1];
    float lgA[8] = {lg0.x, lg0.y, lg0.z, lg0.w, lg1.x, lg1.y, lg1.z, lg1.w};
    float lbA[8] = {lb0.x, lb0.y, lb0.z, lb0.w, lb1.x, lb1.y, lb1.z, lb1.w};
    float btA[8] = {bt0.x, bt0.y, bt0.z, bt0.w, bt1.x, bt1.y, bt1.z, bt1.w};

    float o[8];
#pragma unroll
    for (int k = 0; k < 8; k++) {
        float b = sigm(btA[k]);
        o[k] = (1.f - b) * ((tv[k] - mu) * rstd * lgA[k] + lbA[k]) + b * xv[k];
    }

    if (writeX2) store_split8h(g_X2 + (size_t)n * 512, c, o);

    float* XL = g_XLOC + (size_t)n * DMODEL + c;
    float xl[8];
    if (accumulate) {
        float4 a0 = *(const float4*)(XL);
        float4 a1 = *(const float4*)(XL + 4);
        float aArr[8] = {a0.x, a0.y, a0.z, a0.w, a1.x, a1.y, a1.z, a1.w};
#pragma unroll
        for (int k = 0; k < 8; k++) xl[k] = aArr[k] + o[k];
    } else {
#pragma unroll
        for (int k = 0; k < 8; k++) xl[k] = o[k];
    }
    *(float4*)(XL)     = make_float4(xl[0], xl[1], xl[2], xl[3]);
    *(float4*)(XL + 4) = make_float4(xl[4], xl[5], xl[6], xl[7]);

    if (writeXs) store_split8h(g_Xs + (size_t)n * 512, c, xl);
}

// ---------------- host ------------------------------------------------------------
extern "C" void kernel_launch(void* const* d_in, const int* in_sizes, int n_in,
                              void* d_out, int out_size)
{
    const float* x       = (const float*)d_in[0];
    const int*   ei      = (const int*)  d_in[1];
    const float* Win     = (const float*)d_in[2];
    const float* b_in    = (const float*)d_in[3];
    const float* Wh      = (const float*)d_in[4];
    const float* bh      = (const float*)d_in[5];
    const float* Wg      = (const float*)d_in[6];
    const float* att_src = (const float*)d_in[7];
    const float* att_dst = (const float*)d_in[8];
    const float* bg      = (const float*)d_in[9];
    const float* Wl      = (const float*)d_in[10];
    const float* bl      = (const float*)d_in[11];
    const float* ln_g    = (const float*)d_in[12];
    const float* ln_b    = (const float*)d_in[13];
    const float* betas   = (const float*)d_in[14];
    const float* Wp      = (const float*)d_in[15];
    const float* bp      = (const float*)d_in[16];
    float* out = (float*)d_out;

    cudaFuncSetAttribute(k_gemm, cudaFuncAttributeMaxDynamicSharedMemorySize, SMEM_DYN);

    __half *pXs, *pX2, *pWB, *pHG, *pH, *pGXL;
    cudaGetSymbolAddress((void**)&pXs,  g_Xs);
    cudaGetSymbolAddress((void**)&pX2,  g_X2);
    cudaGetSymbolAddress((void**)&pWB,  g_WB);
    cudaGetSymbolAddress((void**)&pH,   g_H);
    cudaGetSymbolAddress((void**)&pHG,  g_HG);
    cudaGetSymbolAddress((void**)&pGXL, g_GXL);

    const int MT = (NNODE + 127) / 128;   // 782
    Seg z = {nullptr, nullptr, nullptr, 0, 256, 0};

    // launches 1-3, then launch 4 = X0 GEMM (ncu captures the 4th launch)
    k_convX<<<(NNODE * 64 + 255) / 256, 256>>>(x);                       // 1
    k_convW<<<(WB_ROWS * 256 + 255) / 256, 256>>>(Win, Wh, Wg, Wl, Wp); // 2
    k_zero_deg<<<(NNODE + 255) / 256, 256>>>();                          // 3
    {
        Seg s0 = {pX2, b_in, nullptr, 0, 256, 1};
        k_gemm<<<dim3(2, MT), 256, SMEM_DYN>>>(pXs, pWB, NNODE, 2, s0, z, z,
                                               nullptr, nullptr, -1, 0);    // 4 (profiled)
    }

    // CSR build
    k_count<<<(NE_TOT + 255) / 256, 256>>>(ei);
    const int NSB = (NNODE + 1023) / 1024;
    k_scan1<<<NSB, 1024>>>();
    k_scan2<<<1, 128>>>(NSB);
    k_scan3<<<(NNODE + 255) / 256, 256>>>();
    k_fill<<<(NE_TOT + 255) / 256, 256>>>(ei);

    int warpBlocks = (NNODE + 7) / 8;
    for (int i = 0; i < NLAYER; i++) {
        Seg sH  = {pH,   bh + i * DMODEL, nullptr,         1, 256, 2};
        Seg sHG = {pHG,  nullptr,          nullptr,         0, 256, 2};
        Seg sGX = {pGXL, bl + i * DMODEL, bg + i * DMODEL,  0, 256, 2};
        // attention scores fused into the HG (seg 1) epilogue;
        // seg 0 (H) and seg 2 (GXL) run A-hi only: both feed elementwise-only paths.
        k_gemm<<<dim3(6, MT), 256, SMEM_DYN>>>(pX2, pWB + (size_t)(256 + i * 768) * 256,
                                               NNODE, 2, sH, sHG, sGX,
                                               att_src + i * NHEAD * 64,
                                               att_dst + i * NHEAD * 64, 1, 0b101);
        int last = (i == NLAYER - 1);
        k_gat<<<warpBlocks, 256>>>(ln_g + i * DMODEL, ln_b + i * DMODEL, betas + i * DMODEL,
                                   i, !last, last);
    }

    // out = XLOC @ Wp + bp, A-hi only
    {
        Seg s0 = {out, bp, nullptr, 0, 64, 0};
        k_gemm<<<dim3(1, MT), 256, SMEM_DYN>>>(pXs, pWB + (size_t)2560 * 256, NNODE, 1, s0, z, z,
                                               nullptr, nullptr, -1, 1);
    }
}